// round 11
// baseline (speedup 1.0000x reference)
#include <cuda_runtime.h>
#include <cuda_fp16.h>
#include <math.h>

#define BB 4
#define NN 1024
#define CC 768
#define HH 12
#define HD 64
#define QKV3 (3*CC)          // 2304
#define MROWS (2*BB*NN)      // 8192
#define PERSB (HH*NN*HD)     // 786432 elems per (stream,b)

// -------- scratch (device globals; no allocation) --------
__device__ __half g_q  [2*BB*HH*NN*HD];   // [s][b][h][n][d]
__device__ __half g_k  [2*BB*HH*NN*HD];   // [s][b][h][n][d]
__device__ __half g_v  [2*BB*HH*NN*HD];   // [s][b][h][n][d]
__device__ __half g_ctx[2*BB*HH*NN*HD];   // [p][b][h][n][d]
__device__ __half g_x  [MROWS*CC];        // fp16 [before;after]
__device__ __half g_wq [QKV3*CC];         // fp16 W_qkv
__device__ __half g_wp [CC*CC];           // fp16 W_proj

// -------- helpers --------
__device__ __forceinline__ float ex2f(float x) {
    float y; asm("ex2.approx.ftz.f32 %0, %1;" : "=f"(y) : "f"(x)); return y;
}
__device__ __forceinline__ unsigned pack2(float lo, float hi) {
    unsigned r; asm("cvt.rn.f16x2.f32 %0, %1, %2;" : "=r"(r) : "f"(hi), "f"(lo));
    return r;
}
__device__ __forceinline__ void mma16(float* c, const unsigned* a, const unsigned* b) {
    asm volatile("mma.sync.aligned.m16n8k16.row.col.f32.f16.f16.f32 "
        "{%0,%1,%2,%3}, {%4,%5,%6,%7}, {%8,%9}, {%0,%1,%2,%3};"
        : "+f"(c[0]), "+f"(c[1]), "+f"(c[2]), "+f"(c[3])
        : "r"(a[0]), "r"(a[1]), "r"(a[2]), "r"(a[3]), "r"(b[0]), "r"(b[1]));
}
__device__ __forceinline__ void ldsm4(unsigned& r0, unsigned& r1, unsigned& r2,
                                      unsigned& r3, unsigned addr) {
    asm volatile("ldmatrix.sync.aligned.m8n8.x4.shared.b16 {%0,%1,%2,%3}, [%4];"
        : "=r"(r0), "=r"(r1), "=r"(r2), "=r"(r3) : "r"(addr));
}
__device__ __forceinline__ void ldsm4t(unsigned& r0, unsigned& r1, unsigned& r2,
                                       unsigned& r3, unsigned addr) {
    asm volatile("ldmatrix.sync.aligned.m8n8.x4.trans.shared.b16 {%0,%1,%2,%3}, [%4];"
        : "=r"(r0), "=r"(r1), "=r"(r2), "=r"(r3) : "r"(addr));
}
__device__ __forceinline__ unsigned s2u(const void* p) {
    return (unsigned)__cvta_generic_to_shared(p);
}
__device__ __forceinline__ void cp16(unsigned dst, const void* src) {
    asm volatile("cp.async.cg.shared.global [%0], [%1], 16;" :: "r"(dst), "l"(src));
}
#define CPCOMMIT() asm volatile("cp.async.commit_group;")

// GEMM tiling: 128x128 block, K-step 64 (4 x k16), 8 warps (2x4), 3-stage,
// SW128-swizzled staging (128B rows, no pad).
#define SWZ(o)  ((o) ^ (((o) >> 3) & 0x70))
#define GTILE2 16384          // 128 rows x 128 B per operand tile
#define GSTG2  32768          // A + B per stage
#define GSMEM2 (3*GSTG2)      // 98304 B
#define CST    133            // qkv epilogue C stride (floats)

#define PERSIST_GRID 296      // 2 CTAs/SM x 148 SMs

// =====================================================================
// Kernel 0: convert inputs to fp16 (once). 8 floats per thread.
// =====================================================================
#define XQ8 (MROWS*CC/8)     // 786432
#define WQ8 (QKV3*CC/8)      // 221184
#define PQ8 (CC*CC/8)        // 73728
#define PR8 (XQ8+WQ8+PQ8)    // 1081344 = 4224*256

__global__ __launch_bounds__(256) void preround_kernel(
    const float* __restrict__ before, const float* __restrict__ after,
    const float* __restrict__ Wqkv, const float* __restrict__ Wp)
{
    int i = blockIdx.x*256 + threadIdx.x;
    const float* src; __half* dst;
    if (i < XQ8) {
        src = (i < XQ8/2) ? before + (size_t)i*8 : after + (size_t)(i - XQ8/2)*8;
        dst = g_x + (size_t)i*8;
    } else if (i < XQ8 + WQ8) {
        src = Wqkv + (size_t)(i - XQ8)*8;
        dst = g_wq + (size_t)(i - XQ8)*8;
    } else {
        src = Wp + (size_t)(i - XQ8 - WQ8)*8;
        dst = g_wp + (size_t)(i - XQ8 - WQ8)*8;
    }
    float4 v0 = ((const float4*)src)[0];
    float4 v1 = ((const float4*)src)[1];
    uint4 o;
    o.x = pack2(v0.x, v0.y); o.y = pack2(v0.z, v0.w);
    o.z = pack2(v1.x, v1.y); o.w = pack2(v1.z, v1.w);
    *(uint4*)dst = o;
}

// =====================================================================
// Kernel 1: QKV GEMM (fp16, K-step 64, 3-stage, SW128) + fused LN.
// =====================================================================
__global__ __launch_bounds__(256, 2) void qkv_gemm_mma(
    const float* __restrict__ ln_g, const float* __restrict__ ln_b)
{
    extern __shared__ __align__(16) unsigned char sq[];
    __shared__ float s_lng[64], s_lnb[64];
    const int tid = threadIdx.x;
    if (tid < 64) { s_lng[tid] = ln_g[tid]; s_lnb[tid] = ln_b[tid]; }

    const int warp = tid >> 5, lane = tid & 31;
    const int wm = warp >> 2, wn = warp & 3;
    const int g = lane >> 2, t = lane & 3;
    const int mt = blockIdx.y;
    const int bn = blockIdx.x * 128;
    const unsigned smb = s2u(sq);

    const __half* asr[4]; unsigned ad[4];
    const __half* bsr[4]; unsigned bd[4];
    #pragma unroll
    for (int i = 0; i < 4; i++) {
        int id = tid + i*256, r = id >> 3, ch = id & 7;
        unsigned sw = SWZ((unsigned)(r*128 + ch*16));
        asr[i] = g_x + (size_t)(mt*128 + r)*CC + ch*8;
        ad[i]  = smb + sw;
        bsr[i] = g_wq + (size_t)(bn + r)*CC + ch*8;
        bd[i]  = smb + GTILE2 + sw;
    }
    const unsigned aoffl = (lane & 15)*128 + (lane >> 4)*16;
    const unsigned blinl = ((lane & 7) + ((lane >> 4) & 1)*8)*128 + ((lane >> 3) & 1)*16;

    float acc[4][4][4] = {};

    #pragma unroll
    for (int st = 0; st < 2; st++) {
        #pragma unroll
        for (int i = 0; i < 4; i++) {
            cp16(ad[i] + st*GSTG2, asr[i] + st*64);
            cp16(bd[i] + st*GSTG2, bsr[i] + st*64);
        }
        CPCOMMIT();
    }

    unsigned rdo = 0, wro = 2*GSTG2;
    for (int c = 0; c < 12; c++) {
        if (c < 11) { asm volatile("cp.async.wait_group 1;"); }
        else        { asm volatile("cp.async.wait_group 0;"); }
        __syncthreads();
        if (c < 10) {
            #pragma unroll
            for (int i = 0; i < 4; i++) {
                cp16(ad[i] + wro, asr[i] + (c+2)*64);
                cp16(bd[i] + wro, bsr[i] + (c+2)*64);
            }
            CPCOMMIT();
            wro += GSTG2; if (wro == 3*GSTG2) wro = 0;
        }
        const unsigned Ab = smb + rdo;
        const unsigned Bb = Ab + GTILE2;
        rdo += GSTG2; if (rdo == 3*GSTG2) rdo = 0;
        #pragma unroll
        for (int kk = 0; kk < 4; kk++) {
            const unsigned sa = SWZ(aoffl + kk*32);
            const unsigned sb = SWZ(blinl + kk*32);
            unsigned a[4][4], bq[4][2];
            #pragma unroll
            for (int mf = 0; mf < 4; mf++)
                ldsm4(a[mf][0], a[mf][1], a[mf][2], a[mf][3],
                      Ab + sa + (wm*64 + mf*16)*128);
            #pragma unroll
            for (int g2 = 0; g2 < 2; g2++) {
                unsigned r0, r1, r2, r3;
                ldsm4(r0, r1, r2, r3, Bb + sb + (wn*32 + g2*16)*128);
                bq[2*g2][0] = r0; bq[2*g2][1] = r1;
                bq[2*g2+1][0] = r2; bq[2*g2+1][1] = r3;
            }
            #pragma unroll
            for (int mf = 0; mf < 4; mf++)
                #pragma unroll
                for (int nf = 0; nf < 4; nf++)
                    mma16(acc[mf][nf], a[mf], bq[nf]);
        }
    }
    __syncthreads();   // all warps done before Cs aliases staging

    float* Cs = (float*)sq;
    #pragma unroll
    for (int mf = 0; mf < 4; mf++)
        #pragma unroll
        for (int nf = 0; nf < 4; nf++) {
            int row = wm*64 + mf*16 + g, col = wn*32 + nf*8 + 2*t;
            Cs[row*CST + col]       = acc[mf][nf][0];
            Cs[row*CST + col + 1]   = acc[mf][nf][1];
            Cs[(row+8)*CST + col]   = acc[mf][nf][2];
            Cs[(row+8)*CST + col+1] = acc[mf][nf][3];
        }
    __syncthreads();

    {   // LayerNorm over head_dim=64 (2 head-groups per 128-col tile), fp16 out
        int row = tid >> 1, grp = tid & 1;
        const float* src = Cs + row*CST + grp*64;
        float sum = 0.f, sqs = 0.f;
        #pragma unroll
        for (int j = 0; j < 64; j++) { float x = src[j]; sum += x; sqs += x*x; }
        float mu = sum * (1.f/64.f);
        float var = sqs * (1.f/64.f) - mu*mu;
        float rs = rsqrtf(var + 1e-5f);
        int gm = mt*128 + row;
        int s = gm >> 12, b = (gm >> 10) & 3, n = gm & 1023;
        int tq = bn / CC;                       // 0=q,1=k,2=v (tile never straddles)
        int h = ((bn % CC) >> 6) + grp;
        __half* dst = (tq == 0 ? g_q : tq == 1 ? g_k : g_v)
                    + ((((size_t)(s*BB+b)*HH + h)*NN + n)*HD);
        #pragma unroll
        for (int j = 0; j < 64; j += 2) {
            float v0 = (src[j+0]-mu)*rs*s_lng[j+0] + s_lnb[j+0];
            float v1 = (src[j+1]-mu)*rs*s_lng[j+1] + s_lnb[j+1];
            *(__half2*)(dst + j) = __floats2half2_rn(v0, v1);
        }
    }
}

// =====================================================================
// Kernel 2: attention, fp16 m16n8k16, PERSISTENT (grid-stride over 768
// tiles) with warp-parity STAGGER of the two kv half-tiles so half the
// warps run softmax (MUFU) while the other half runs mma (tensor).
// 256 thr = 8 warps, q-tile 128, kv-tile 128, 2 CTAs/SM.
// =====================================================================
#define ARS 144               // 64 halves + 8 pad = 144 B per row
#define QB  0
#define KB0 (128*ARS)         // 18432
#define VB0 (KB0 + 2*128*ARS) // 55296
#define ATTN_SMEM (VB0 + 2*128*ARS)   // 92160

__global__ __launch_bounds__(256, 2) void attn_mma() {
    extern __shared__ __align__(16) unsigned char sa[];
    const unsigned smb = s2u(sa);

    const int tid = threadIdx.x, w = tid >> 5, lane = tid & 31;
    const int g = lane >> 2, t = lane & 3;

    const unsigned aoffA = ((lane & 15)*ARS + (lane >> 4)*16);
    const unsigned boffK = (((lane & 7) + ((lane >> 4) & 1)*8)*ARS + ((lane >> 3) & 1)*16);
    const unsigned boffV = (((lane & 7) + ((lane >> 3) & 1)*8)*ARS + (lane >> 4)*16);

    int srow[4], sch[4];
    #pragma unroll
    for (int i = 0; i < 4; i++) {
        int id = tid + i*256; srow[i] = id >> 3; sch[i] = id & 7;
    }
    const int h0 = w & 1;    // stagger: odd warps process half 1 first

    for (int bid = blockIdx.x; bid < 768; bid += gridDim.x) {
        const int qt = bid & 7;
        const int h  = (bid >> 3) % 12;
        const int b  = (bid / 96) & 3;
        const int p  = bid / 384;
        const int qs = 1 - p, kvs = p;

        const __half* qptr = g_q + (((size_t)(qs*BB+b)*HH + h)*NN + qt*128)*HD;
        const __half* kptr = g_k + (((size_t)(kvs*BB+b)*HH + h)*NN)*HD;
        const __half* vptr = g_v + (((size_t)(kvs*BB+b)*HH + h)*NN)*HD;

        // prefetch kc=0 into buffer 0
        #pragma unroll
        for (int i = 0; i < 4; i++) {
            cp16(smb + KB0 + srow[i]*ARS + sch[i]*16, kptr + srow[i]*64 + sch[i]*8);
            cp16(smb + VB0 + srow[i]*ARS + sch[i]*16, vptr + srow[i]*64 + sch[i]*8);
        }
        CPCOMMIT();

        // stage Q (128x64 fp16) and hoist fragments to registers
        #pragma unroll
        for (int i = 0; i < 4; i++) {
            int id = tid + i*256, row = id >> 3, ch = id & 7;
            *(uint4*)(sa + QB + row*ARS + ch*16) = *(const uint4*)(qptr + row*64 + ch*8);
        }
        __syncthreads();
        unsigned q[4][4];
        #pragma unroll
        for (int kk = 0; kk < 4; kk++)
            ldsm4(q[kk][0], q[kk][1], q[kk][2], q[kk][3],
                  smb + QB + (w*16)*ARS + kk*32 + aoffA);

        const float SC = 0.125f * 1.44269504088896f;   // scale * log2(e)
        float o[8][4] = {};
        float m0 = -1e30f, m1 = -1e30f, l0 = 0.f, l1 = 0.f;

        for (int kc = 0; kc < 8; kc++) {
            __syncthreads();                   // readers of buf[(kc+1)&1] done
            if (kc < 7) {
                const __half* kp = kptr + (kc+1)*128*64;
                const __half* vp = vptr + (kc+1)*128*64;
                const unsigned kb = smb + KB0 + ((kc+1)&1)*(128*ARS);
                const unsigned vb = smb + VB0 + ((kc+1)&1)*(128*ARS);
                #pragma unroll
                for (int i = 0; i < 4; i++) {
                    cp16(kb + srow[i]*ARS + sch[i]*16, kp + srow[i]*64 + sch[i]*8);
                    cp16(vb + srow[i]*ARS + sch[i]*16, vp + srow[i]*64 + sch[i]*8);
                }
                CPCOMMIT();
                asm volatile("cp.async.wait_group 1;");
            } else {
                asm volatile("cp.async.wait_group 0;");
            }
            __syncthreads();                   // buf[kc&1] visible

            const unsigned Kb = smb + KB0 + (kc&1)*(128*ARS);
            const unsigned Vb = smb + VB0 + (kc&1)*(128*ARS);

            #pragma unroll
            for (int hh = 0; hh < 2; hh++) {
                const int half = hh ^ h0;      // warp-parity stagger
                const unsigned Kh = Kb + half*64*ARS;
                const unsigned Vh = Vb + half*64*ARS;

                // S = Q K^T over 64 kv columns
                float s[8][4] = {};
                #pragma unroll
                for (int kk = 0; kk < 4; kk++) {
                    #pragma unroll
                    for (int j2 = 0; j2 < 4; j2++) {
                        unsigned r0, r1, r2, r3;
                        ldsm4(r0, r1, r2, r3, Kh + (j2*16)*ARS + kk*32 + boffK);
                        unsigned bf0[2] = {r0, r1}, bf1[2] = {r2, r3};
                        mma16(s[2*j2], q[kk], bf0);
                        mma16(s[2*j2+1], q[kk], bf1);
                    }
                }

                // online softmax (warp-local; rows g and g+8)
                float mx0 = -1e30f, mx1 = -1e30f;
                #pragma unroll
                for (int nf = 0; nf < 8; nf++) {
                    #pragma unroll
                    for (int j = 0; j < 4; j++) s[nf][j] *= SC;
                    mx0 = fmaxf(mx0, fmaxf(s[nf][0], s[nf][1]));
                    mx1 = fmaxf(mx1, fmaxf(s[nf][2], s[nf][3]));
                }
                mx0 = fmaxf(mx0, __shfl_xor_sync(0xffffffffu, mx0, 1));
                mx0 = fmaxf(mx0, __shfl_xor_sync(0xffffffffu, mx0, 2));
                mx1 = fmaxf(mx1, __shfl_xor_sync(0xffffffffu, mx1, 1));
                mx1 = fmaxf(mx1, __shfl_xor_sync(0xffffffffu, mx1, 2));
                float M0 = fmaxf(m0, mx0), M1 = fmaxf(m1, mx1);
                float c0 = ex2f(m0 - M0), c1 = ex2f(m1 - M1);
                float ls0 = 0.f, ls1 = 0.f;
                #pragma unroll
                for (int nf = 0; nf < 8; nf++) {
                    s[nf][0] = ex2f(s[nf][0] - M0);
                    s[nf][1] = ex2f(s[nf][1] - M0);
                    s[nf][2] = ex2f(s[nf][2] - M1);
                    s[nf][3] = ex2f(s[nf][3] - M1);
                    ls0 += s[nf][0] + s[nf][1];
                    ls1 += s[nf][2] + s[nf][3];
                }
                ls0 += __shfl_xor_sync(0xffffffffu, ls0, 1);
                ls0 += __shfl_xor_sync(0xffffffffu, ls0, 2);
                ls1 += __shfl_xor_sync(0xffffffffu, ls1, 1);
                ls1 += __shfl_xor_sync(0xffffffffu, ls1, 2);
                l0 = l0*c0 + ls0; l1 = l1*c1 + ls1;
                m0 = M0; m1 = M1;
                #pragma unroll
                for (int nf = 0; nf < 8; nf++) {
                    o[nf][0] *= c0; o[nf][1] *= c0; o[nf][2] *= c1; o[nf][3] *= c1;
                }

                // O += P @ V : P packed from accumulators, V via ldmatrix.trans
                #pragma unroll
                for (int kc2 = 0; kc2 < 4; kc2++) {
                    unsigned a[4];
                    a[0] = pack2(s[2*kc2][0],   s[2*kc2][1]);
                    a[1] = pack2(s[2*kc2][2],   s[2*kc2][3]);
                    a[2] = pack2(s[2*kc2+1][0], s[2*kc2+1][1]);
                    a[3] = pack2(s[2*kc2+1][2], s[2*kc2+1][3]);
                    #pragma unroll
                    for (int j = 0; j < 4; j++) {
                        unsigned r0, r1, r2, r3;
                        ldsm4t(r0, r1, r2, r3, Vh + (kc2*16)*ARS + j*32 + boffV);
                        unsigned bf0[2] = {r0, r1}, bf1[2] = {r2, r3};
                        mma16(o[2*j], a, bf0);
                        mma16(o[2*j+1], a, bf1);
                    }
                }
            }
        }

        const int qrow = qt*128 + w*16;
        float inv0 = 1.f / l0, inv1 = 1.f / l1;
        __half* op = g_ctx + (((size_t)(p*BB+b)*HH + h)*NN + qrow)*HD;
        #pragma unroll
        for (int nf = 0; nf < 8; nf++) {
            *(__half2*)(op + g*64 + nf*8 + 2*t) =
                __floats2half2_rn(o[nf][0]*inv0, o[nf][1]*inv0);
            *(__half2*)(op + (g+8)*64 + nf*8 + 2*t) =
                __floats2half2_rn(o[nf][2]*inv1, o[nf][3]*inv1);
        }
    }
}

// =====================================================================
// Kernel 3: projection GEMM (fp16, K-step 64 = one head, 3-stage, SW128),
// PERSISTENT grid-stride over the 384 tiles. + bias + q-residual -> f32.
// =====================================================================
__global__ __launch_bounds__(256, 2) void proj_gemm_mma(
    const float* __restrict__ bias, float* __restrict__ out)
{
    extern __shared__ __align__(16) unsigned char sp[];
    const int tid = threadIdx.x;
    const int warp = tid >> 5, lane = tid & 31;
    const int wm = warp >> 2, wn = warp & 3;
    const int g = lane >> 2, t = lane & 3;
    const unsigned smb = s2u(sp);

    const unsigned aoffl = (lane & 15)*128 + (lane >> 4)*16;
    const unsigned blinl = ((lane & 7) + ((lane >> 4) & 1)*8)*128 + ((lane >> 3) & 1)*16;

    int tr[4], tch[4]; unsigned tsw[4];
    #pragma unroll
    for (int i = 0; i < 4; i++) {
        int id = tid + i*256; tr[i] = id >> 3; tch[i] = id & 7;
        tsw[i] = SWZ((unsigned)(tr[i]*128 + tch[i]*16));
    }

    for (int bid = blockIdx.x; bid < 384; bid += gridDim.x) {
        const int mt = bid / 6;
        const int bn = (bid % 6) * 128;

        const __half* actx[4]; unsigned ad[4];
        const __half* bsr[4]; unsigned bd[4];
        #pragma unroll
        for (int i = 0; i < 4; i++) {
            int gm = mt*128 + tr[i];
            int pp = gm >> 12, b2 = (gm >> 10) & 3, n = gm & 1023;
            actx[i] = g_ctx + (size_t)(pp*BB + b2)*PERSB + (size_t)n*HD + tch[i]*8;
            ad[i]   = smb + tsw[i];
            bsr[i]  = g_wp + (size_t)(bn + tr[i])*CC + tch[i]*8;
            bd[i]   = smb + GTILE2 + tsw[i];
        }

        float acc[4][4][4] = {};

        #pragma unroll
        for (int st = 0; st < 2; st++) {
            #pragma unroll
            for (int i = 0; i < 4; i++) {
                cp16(ad[i] + st*GSTG2, actx[i] + (size_t)st*(NN*HD));
                cp16(bd[i] + st*GSTG2, bsr[i] + st*64);
            }
            CPCOMMIT();
        }

        unsigned rdo = 0, wro = 2*GSTG2;
        for (int c = 0; c < 12; c++) {
            if (c < 11) { asm volatile("cp.async.wait_group 1;"); }
            else        { asm volatile("cp.async.wait_group 0;"); }
            __syncthreads();
            if (c < 10) {
                #pragma unroll
                for (int i = 0; i < 4; i++) {
                    cp16(ad[i] + wro, actx[i] + (size_t)(c+2)*(NN*HD));
                    cp16(bd[i] + wro, bsr[i] + (c+2)*64);
                }
                CPCOMMIT();
                wro += GSTG2; if (wro == 3*GSTG2) wro = 0;
            }
            const unsigned Ab = smb + rdo;
            const unsigned Bb = Ab + GTILE2;
            rdo += GSTG2; if (rdo == 3*GSTG2) rdo = 0;
            #pragma unroll
            for (int kk = 0; kk < 4; kk++) {
                const unsigned sa2 = SWZ(aoffl + kk*32);
                const unsigned sb2 = SWZ(blinl + kk*32);
                unsigned a[4][4], bq[4][2];
                #pragma unroll
                for (int mf = 0; mf < 4; mf++)
                    ldsm4(a[mf][0], a[mf][1], a[mf][2], a[mf][3],
                          Ab + sa2 + (wm*64 + mf*16)*128);
                #pragma unroll
                for (int g2 = 0; g2 < 2; g2++) {
                    unsigned r0, r1, r2, r3;
                    ldsm4(r0, r1, r2, r3, Bb + sb2 + (wn*32 + g2*16)*128);
                    bq[2*g2][0] = r0; bq[2*g2][1] = r1;
                    bq[2*g2+1][0] = r2; bq[2*g2+1][1] = r3;
                }
                #pragma unroll
                for (int mf = 0; mf < 4; mf++)
                    #pragma unroll
                    for (int nf = 0; nf < 4; nf++)
                        mma16(acc[mf][nf], a[mf], bq[nf]);
            }
        }

        // epilogue: bias + fp16 flat-q residual -> f32 d_out
        #pragma unroll
        for (int mf = 0; mf < 4; mf++) {
            #pragma unroll
            for (int rr = 0; rr < 2; rr++) {
                int gm = mt*128 + wm*64 + mf*16 + g + rr*8;
                int pp = gm >> 12, b2 = (gm >> 10) & 3, n = gm & 1023;
                const __half* qres = g_q + (size_t)((1-pp)*BB + b2)*PERSB + (size_t)n*CC;
                #pragma unroll
                for (int nf = 0; nf < 4; nf++) {
                    int col = bn + wn*32 + nf*8 + 2*t;
                    float2 qr = __half22float2(*(const __half2*)(qres + col));
                    float2 r;
                    r.x = acc[mf][nf][2*rr+0] + __ldg(bias + col)   + qr.x;
                    r.y = acc[mf][nf][2*rr+1] + __ldg(bias + col+1) + qr.y;
                    *(float2*)(out + (size_t)gm*CC + col) = r;
                }
            }
        }
    }
}

// =====================================================================
extern "C" void kernel_launch(void* const* d_in, const int* in_sizes, int n_in,
                              void* d_out, int out_size) {
    const float* before = (const float*)d_in[0];
    const float* after  = (const float*)d_in[1];
    const float* W_qkv  = (const float*)d_in[2];
    const float* ln_g   = (const float*)d_in[3];
    const float* ln_b   = (const float*)d_in[4];
    const float* W_proj = (const float*)d_in[5];
    const float* b_proj = (const float*)d_in[6];
    float* out = (float*)d_out;

    const int gemm_smem = GSMEM2;             // 98304 (>= Cs 68096)
    const int attn_smem = ATTN_SMEM;          // 92160

    // 0) convert inputs to fp16
    preround_kernel<<<PR8/256, 256>>>(before, after, W_qkv, W_proj);

    // 1) QKV GEMM + fused LN: grid (2304/128, 8192/128)
    {
        cudaFuncSetAttribute(qkv_gemm_mma, cudaFuncAttributeMaxDynamicSharedMemorySize, gemm_smem);
        dim3 grid(QKV3/128, MROWS/128);
        qkv_gemm_mma<<<grid, 256, gemm_smem>>>(ln_g, ln_b);
    }
    // 2) Attention: persistent 296 blocks over 768 tiles
    {
        cudaFuncSetAttribute(attn_mma, cudaFuncAttributeMaxDynamicSharedMemorySize, attn_smem);
        attn_mma<<<PERSIST_GRID, 256, attn_smem>>>();
    }
    // 3) Projection GEMM: persistent 296 blocks over 384 tiles
    {
        cudaFuncSetAttribute(proj_gemm_mma, cudaFuncAttributeMaxDynamicSharedMemorySize, gemm_smem);
        proj_gemm_mma<<<PERSIST_GRID, 256, gemm_smem>>>(b_proj, out);
    }
}

// round 12
// speedup vs baseline: 1.1484x; 1.1484x over previous
#include <cuda_runtime.h>
#include <cuda_fp16.h>
#include <math.h>

#define BB 4
#define NN 1024
#define CC 768
#define HH 12
#define HD 64
#define QKV3 (3*CC)          // 2304
#define MROWS (2*BB*NN)      // 8192
#define PERSB (HH*NN*HD)     // 786432 elems per (stream,b)

// -------- scratch (device globals; no allocation) --------
__device__ __half g_q  [2*BB*HH*NN*HD];   // [s][b][h][n][d]
__device__ __half g_k  [2*BB*HH*NN*HD];   // [s][b][h][n][d]
__device__ __half g_v  [2*BB*HH*NN*HD];   // [s][b][h][n][d]
__device__ __half g_ctx[2*BB*HH*NN*HD];   // [p][b][h][n][d]
__device__ __half g_x  [MROWS*CC];        // fp16 [before;after]
__device__ __half g_wq [QKV3*CC];         // fp16 W_qkv
__device__ __half g_wp [CC*CC];           // fp16 W_proj

// -------- helpers --------
__device__ __forceinline__ float ex2f(float x) {
    float y; asm("ex2.approx.ftz.f32 %0, %1;" : "=f"(y) : "f"(x)); return y;
}
__device__ __forceinline__ unsigned pack2(float lo, float hi) {
    unsigned r; asm("cvt.rn.f16x2.f32 %0, %1, %2;" : "=r"(r) : "f"(hi), "f"(lo));
    return r;
}
__device__ __forceinline__ void mma16(float* c, const unsigned* a, const unsigned* b) {
    asm volatile("mma.sync.aligned.m16n8k16.row.col.f32.f16.f16.f32 "
        "{%0,%1,%2,%3}, {%4,%5,%6,%7}, {%8,%9}, {%0,%1,%2,%3};"
        : "+f"(c[0]), "+f"(c[1]), "+f"(c[2]), "+f"(c[3])
        : "r"(a[0]), "r"(a[1]), "r"(a[2]), "r"(a[3]), "r"(b[0]), "r"(b[1]));
}
__device__ __forceinline__ void ldsm4(unsigned& r0, unsigned& r1, unsigned& r2,
                                      unsigned& r3, unsigned addr) {
    asm volatile("ldmatrix.sync.aligned.m8n8.x4.shared.b16 {%0,%1,%2,%3}, [%4];"
        : "=r"(r0), "=r"(r1), "=r"(r2), "=r"(r3) : "r"(addr));
}
__device__ __forceinline__ void ldsm4t(unsigned& r0, unsigned& r1, unsigned& r2,
                                       unsigned& r3, unsigned addr) {
    asm volatile("ldmatrix.sync.aligned.m8n8.x4.trans.shared.b16 {%0,%1,%2,%3}, [%4];"
        : "=r"(r0), "=r"(r1), "=r"(r2), "=r"(r3) : "r"(addr));
}
__device__ __forceinline__ unsigned s2u(const void* p) {
    return (unsigned)__cvta_generic_to_shared(p);
}
__device__ __forceinline__ void cp16(unsigned dst, const void* src) {
    asm volatile("cp.async.cg.shared.global [%0], [%1], 16;" :: "r"(dst), "l"(src));
}
#define CPCOMMIT() asm volatile("cp.async.commit_group;")

// GEMM tiling: 128x128 block, 128 thr = 4 warps (2m x 2n), warp tile 64x64,
// K-step 64 (4 x k16), 3-stage SW128-swizzled staging.
#define SWZ(o)  ((o) ^ (((o) >> 3) & 0x70))
#define GTILE2 16384          // 128 rows x 128 B per operand tile
#define GSTG2  32768          // A + B per stage
#define GSMEM2 (3*GSTG2)      // 98304 B

// =====================================================================
// Kernel 0: convert inputs to fp16 (once). 8 floats per thread.
// =====================================================================
#define XQ8 (MROWS*CC/8)     // 786432
#define WQ8 (QKV3*CC/8)      // 221184
#define PQ8 (CC*CC/8)        // 73728
#define PR8 (XQ8+WQ8+PQ8)    // 1081344 = 4224*256

__global__ __launch_bounds__(256) void preround_kernel(
    const float* __restrict__ before, const float* __restrict__ after,
    const float* __restrict__ Wqkv, const float* __restrict__ Wp)
{
    int i = blockIdx.x*256 + threadIdx.x;
    const float* src; __half* dst;
    if (i < XQ8) {
        src = (i < XQ8/2) ? before + (size_t)i*8 : after + (size_t)(i - XQ8/2)*8;
        dst = g_x + (size_t)i*8;
    } else if (i < XQ8 + WQ8) {
        src = Wqkv + (size_t)(i - XQ8)*8;
        dst = g_wq + (size_t)(i - XQ8)*8;
    } else {
        src = Wp + (size_t)(i - XQ8 - WQ8)*8;
        dst = g_wp + (size_t)(i - XQ8 - WQ8)*8;
    }
    float4 v0 = ((const float4*)src)[0];
    float4 v1 = ((const float4*)src)[1];
    uint4 o;
    o.x = pack2(v0.x, v0.y); o.y = pack2(v0.z, v0.w);
    o.z = pack2(v1.x, v1.y); o.w = pack2(v1.z, v1.w);
    *(uint4*)dst = o;
}

// =====================================================================
// Kernel 1: QKV GEMM (fp16, warp tile 64x64, 4 warps) + REGISTER LayerNorm.
// wn warp-column == one 64-wide head -> LN reduces with 2 shfls, no smem C.
// =====================================================================
__global__ __launch_bounds__(128, 2) void qkv_gemm_mma(
    const float* __restrict__ ln_g, const float* __restrict__ ln_b)
{
    extern __shared__ __align__(16) unsigned char sq[];
    __shared__ float s_lng[64], s_lnb[64];
    const int tid = threadIdx.x;
    if (tid < 64) { s_lng[tid] = ln_g[tid]; s_lnb[tid] = ln_b[tid]; }

    const int warp = tid >> 5, lane = tid & 31;
    const int wm = warp >> 1, wn = warp & 1;
    const int g = lane >> 2, t = lane & 3;
    const int mt = blockIdx.y;
    const int bn = blockIdx.x * 128;
    const unsigned smb = s2u(sq);

    // staging: 8 A + 8 B cp16 per thread per stage (128 rows x 8 chunks each)
    const __half* asr[8]; unsigned ad[8];
    const __half* bsr[8]; unsigned bd[8];
    #pragma unroll
    for (int i = 0; i < 8; i++) {
        int id = tid + i*128, r = id >> 3, ch = id & 7;
        unsigned sw = SWZ((unsigned)(r*128 + ch*16));
        asr[i] = g_x + (size_t)(mt*128 + r)*CC + ch*8;
        ad[i]  = smb + sw;
        bsr[i] = g_wq + (size_t)(bn + r)*CC + ch*8;
        bd[i]  = smb + GTILE2 + sw;
    }
    const unsigned aoffl = (lane & 15)*128 + (lane >> 4)*16;
    const unsigned blinl = ((lane & 7) + ((lane >> 4) & 1)*8)*128 + ((lane >> 3) & 1)*16;

    float acc[4][8][4] = {};

    #pragma unroll
    for (int st = 0; st < 2; st++) {
        #pragma unroll
        for (int i = 0; i < 8; i++) {
            cp16(ad[i] + st*GSTG2, asr[i] + st*64);
            cp16(bd[i] + st*GSTG2, bsr[i] + st*64);
        }
        CPCOMMIT();
    }

    unsigned rdo = 0, wro = 2*GSTG2;
    for (int c = 0; c < 12; c++) {
        if (c < 11) { asm volatile("cp.async.wait_group 1;"); }
        else        { asm volatile("cp.async.wait_group 0;"); }
        __syncthreads();
        if (c < 10) {
            #pragma unroll
            for (int i = 0; i < 8; i++) {
                cp16(ad[i] + wro, asr[i] + (c+2)*64);
                cp16(bd[i] + wro, bsr[i] + (c+2)*64);
            }
            CPCOMMIT();
            wro += GSTG2; if (wro == 3*GSTG2) wro = 0;
        }
        const unsigned Ab = smb + rdo;
        const unsigned Bb = Ab + GTILE2;
        rdo += GSTG2; if (rdo == 3*GSTG2) rdo = 0;
        #pragma unroll
        for (int kk = 0; kk < 4; kk++) {
            const unsigned sa2 = SWZ(aoffl + kk*32);
            const unsigned sb2 = SWZ(blinl + kk*32);
            unsigned a[4][4], bq[8][2];
            #pragma unroll
            for (int mf = 0; mf < 4; mf++)
                ldsm4(a[mf][0], a[mf][1], a[mf][2], a[mf][3],
                      Ab + sa2 + (wm*64 + mf*16)*128);
            #pragma unroll
            for (int g2 = 0; g2 < 4; g2++) {
                unsigned r0, r1, r2, r3;
                ldsm4(r0, r1, r2, r3, Bb + sb2 + (wn*64 + g2*16)*128);
                bq[2*g2][0] = r0; bq[2*g2][1] = r1;
                bq[2*g2+1][0] = r2; bq[2*g2+1][1] = r3;
            }
            #pragma unroll
            for (int mf = 0; mf < 4; mf++)
                #pragma unroll
                for (int nf = 0; nf < 8; nf++)
                    mma16(acc[mf][nf], a[mf], bq[nf]);
        }
    }

    // ---- register-resident LayerNorm epilogue ----
    // warp column wn covers exactly one head (64 cols); thread holds 16 cols
    // of rows {.., g, g+8, ..}. Row sums complete with shfl over the t-quad.
    const int cb = bn + wn*64;
    const int tq = cb / CC;                 // 0=q,1=k,2=v
    const int h  = (cb % CC) >> 6;
    // stream decode (whole 128-row tile is within one (s,b) block)
    const int gm0 = mt*128;
    const int s = gm0 >> 12, b = (gm0 >> 10) & 3;
    __half* dbase = (tq == 0 ? g_q : tq == 1 ? g_k : g_v)
                  + ((((size_t)(s*BB+b)*HH + h)*NN) + (gm0 & 1023))*HD;

    #pragma unroll
    for (int mf = 0; mf < 4; mf++) {
        float sum0 = 0.f, sq0 = 0.f, sum1 = 0.f, sq1 = 0.f;
        #pragma unroll
        for (int nf = 0; nf < 8; nf++) {
            float a0 = acc[mf][nf][0], a1 = acc[mf][nf][1];
            float a2 = acc[mf][nf][2], a3 = acc[mf][nf][3];
            sum0 += a0 + a1; sq0 += a0*a0 + a1*a1;
            sum1 += a2 + a3; sq1 += a2*a2 + a3*a3;
        }
        sum0 += __shfl_xor_sync(0xffffffffu, sum0, 1);
        sum0 += __shfl_xor_sync(0xffffffffu, sum0, 2);
        sq0  += __shfl_xor_sync(0xffffffffu, sq0, 1);
        sq0  += __shfl_xor_sync(0xffffffffu, sq0, 2);
        sum1 += __shfl_xor_sync(0xffffffffu, sum1, 1);
        sum1 += __shfl_xor_sync(0xffffffffu, sum1, 2);
        sq1  += __shfl_xor_sync(0xffffffffu, sq1, 1);
        sq1  += __shfl_xor_sync(0xffffffffu, sq1, 2);
        float mu0 = sum0 * (1.f/64.f);
        float rs0 = rsqrtf(sq0 * (1.f/64.f) - mu0*mu0 + 1e-5f);
        float mu1 = sum1 * (1.f/64.f);
        float rs1 = rsqrtf(sq1 * (1.f/64.f) - mu1*mu1 + 1e-5f);

        int r0 = wm*64 + mf*16 + g;         // local row in tile
        __half* d0 = dbase + (size_t)r0*HD;
        __half* d1 = dbase + (size_t)(r0+8)*HD;
        #pragma unroll
        for (int nf = 0; nf < 8; nf++) {
            int col = nf*8 + 2*t;
            float g0 = s_lng[col], g1 = s_lng[col+1];
            float b0 = s_lnb[col], b1 = s_lnb[col+1];
            *(__half2*)(d0 + col) = __floats2half2_rn(
                (acc[mf][nf][0]-mu0)*rs0*g0 + b0,
                (acc[mf][nf][1]-mu0)*rs0*g1 + b1);
            *(__half2*)(d1 + col) = __floats2half2_rn(
                (acc[mf][nf][2]-mu1)*rs1*g0 + b0,
                (acc[mf][nf][3]-mu1)*rs1*g1 + b1);
        }
    }
}

// =====================================================================
// Kernel 2: attention (r10-proven form): fp16 m16n8k16, 256 thr = 8 warps,
// q-tile 128, kv-tile 128, 2 CTAs/SM, Q in regs, P packed from accums.
// =====================================================================
#define ARS 144               // 64 halves + 8 pad = 144 B per row
#define QB  0
#define KB0 (128*ARS)         // 18432
#define VB0 (KB0 + 2*128*ARS) // 55296
#define ATTN_SMEM (VB0 + 2*128*ARS)   // 92160

__global__ __launch_bounds__(256, 2) void attn_mma() {
    extern __shared__ __align__(16) unsigned char sa[];
    const unsigned smb = s2u(sa);

    const int bx = blockIdx.x;
    const int qt = bx & 7;
    const int h  = (bx >> 3) % 12;
    const int b  = (bx / 96) & 3;
    const int p  = bx / 384;
    const int qs = 1 - p, kvs = p;

    const __half* qptr = g_q + (((size_t)(qs*BB+b)*HH + h)*NN + qt*128)*HD;
    const __half* kptr = g_k + (((size_t)(kvs*BB+b)*HH + h)*NN)*HD;
    const __half* vptr = g_v + (((size_t)(kvs*BB+b)*HH + h)*NN)*HD;

    const int tid = threadIdx.x, w = tid >> 5, lane = tid & 31;
    const int g = lane >> 2, t = lane & 3;

    const unsigned aoffA = ((lane & 15)*ARS + (lane >> 4)*16);
    const unsigned boffK = (((lane & 7) + ((lane >> 4) & 1)*8)*ARS + ((lane >> 3) & 1)*16);
    const unsigned boffV = (((lane & 7) + ((lane >> 3) & 1)*8)*ARS + (lane >> 4)*16);

    int srow[4], sch[4];
    #pragma unroll
    for (int i = 0; i < 4; i++) {
        int id = tid + i*256; srow[i] = id >> 3; sch[i] = id & 7;
    }

    #pragma unroll
    for (int i = 0; i < 4; i++) {
        cp16(smb + KB0 + srow[i]*ARS + sch[i]*16, kptr + srow[i]*64 + sch[i]*8);
        cp16(smb + VB0 + srow[i]*ARS + sch[i]*16, vptr + srow[i]*64 + sch[i]*8);
    }
    CPCOMMIT();

    #pragma unroll
    for (int i = 0; i < 4; i++) {
        int id = tid + i*256, row = id >> 3, ch = id & 7;
        *(uint4*)(sa + QB + row*ARS + ch*16) = *(const uint4*)(qptr + row*64 + ch*8);
    }
    __syncthreads();
    unsigned q[4][4];
    #pragma unroll
    for (int kk = 0; kk < 4; kk++)
        ldsm4(q[kk][0], q[kk][1], q[kk][2], q[kk][3],
              smb + QB + (w*16)*ARS + kk*32 + aoffA);

    const float SC = 0.125f * 1.44269504088896f;   // scale * log2(e)
    float o[8][4] = {};
    float m0 = -1e30f, m1 = -1e30f, l0 = 0.f, l1 = 0.f;

    for (int kc = 0; kc < 8; kc++) {
        __syncthreads();
        if (kc < 7) {
            const __half* kp = kptr + (kc+1)*128*64;
            const __half* vp = vptr + (kc+1)*128*64;
            const unsigned kb = smb + KB0 + ((kc+1)&1)*(128*ARS);
            const unsigned vb = smb + VB0 + ((kc+1)&1)*(128*ARS);
            #pragma unroll
            for (int i = 0; i < 4; i++) {
                cp16(kb + srow[i]*ARS + sch[i]*16, kp + srow[i]*64 + sch[i]*8);
                cp16(vb + srow[i]*ARS + sch[i]*16, vp + srow[i]*64 + sch[i]*8);
            }
            CPCOMMIT();
            asm volatile("cp.async.wait_group 1;");
        } else {
            asm volatile("cp.async.wait_group 0;");
        }
        __syncthreads();

        const unsigned Kb = smb + KB0 + (kc&1)*(128*ARS);
        const unsigned Vb = smb + VB0 + (kc&1)*(128*ARS);

        #pragma unroll
        for (int half = 0; half < 2; half++) {
            const unsigned Kh = Kb + half*64*ARS;
            const unsigned Vh = Vb + half*64*ARS;

            float s[8][4] = {};
            #pragma unroll
            for (int kk = 0; kk < 4; kk++) {
                #pragma unroll
                for (int j2 = 0; j2 < 4; j2++) {
                    unsigned r0, r1, r2, r3;
                    ldsm4(r0, r1, r2, r3, Kh + (j2*16)*ARS + kk*32 + boffK);
                    unsigned bf0[2] = {r0, r1}, bf1[2] = {r2, r3};
                    mma16(s[2*j2], q[kk], bf0);
                    mma16(s[2*j2+1], q[kk], bf1);
                }
            }

            float mx0 = -1e30f, mx1 = -1e30f;
            #pragma unroll
            for (int nf = 0; nf < 8; nf++) {
                #pragma unroll
                for (int j = 0; j < 4; j++) s[nf][j] *= SC;
                mx0 = fmaxf(mx0, fmaxf(s[nf][0], s[nf][1]));
                mx1 = fmaxf(mx1, fmaxf(s[nf][2], s[nf][3]));
            }
            mx0 = fmaxf(mx0, __shfl_xor_sync(0xffffffffu, mx0, 1));
            mx0 = fmaxf(mx0, __shfl_xor_sync(0xffffffffu, mx0, 2));
            mx1 = fmaxf(mx1, __shfl_xor_sync(0xffffffffu, mx1, 1));
            mx1 = fmaxf(mx1, __shfl_xor_sync(0xffffffffu, mx1, 2));
            float M0 = fmaxf(m0, mx0), M1 = fmaxf(m1, mx1);
            float c0 = ex2f(m0 - M0), c1 = ex2f(m1 - M1);
            float ls0 = 0.f, ls1 = 0.f;
            #pragma unroll
            for (int nf = 0; nf < 8; nf++) {
                s[nf][0] = ex2f(s[nf][0] - M0);
                s[nf][1] = ex2f(s[nf][1] - M0);
                s[nf][2] = ex2f(s[nf][2] - M1);
                s[nf][3] = ex2f(s[nf][3] - M1);
                ls0 += s[nf][0] + s[nf][1];
                ls1 += s[nf][2] + s[nf][3];
            }
            ls0 += __shfl_xor_sync(0xffffffffu, ls0, 1);
            ls0 += __shfl_xor_sync(0xffffffffu, ls0, 2);
            ls1 += __shfl_xor_sync(0xffffffffu, ls1, 1);
            ls1 += __shfl_xor_sync(0xffffffffu, ls1, 2);
            l0 = l0*c0 + ls0; l1 = l1*c1 + ls1;
            m0 = M0; m1 = M1;
            #pragma unroll
            for (int nf = 0; nf < 8; nf++) {
                o[nf][0] *= c0; o[nf][1] *= c0; o[nf][2] *= c1; o[nf][3] *= c1;
            }

            #pragma unroll
            for (int kc2 = 0; kc2 < 4; kc2++) {
                unsigned a[4];
                a[0] = pack2(s[2*kc2][0],   s[2*kc2][1]);
                a[1] = pack2(s[2*kc2][2],   s[2*kc2][3]);
                a[2] = pack2(s[2*kc2+1][0], s[2*kc2+1][1]);
                a[3] = pack2(s[2*kc2+1][2], s[2*kc2+1][3]);
                #pragma unroll
                for (int j = 0; j < 4; j++) {
                    unsigned r0, r1, r2, r3;
                    ldsm4t(r0, r1, r2, r3, Vh + (kc2*16)*ARS + j*32 + boffV);
                    unsigned bf0[2] = {r0, r1}, bf1[2] = {r2, r3};
                    mma16(o[2*j], a, bf0);
                    mma16(o[2*j+1], a, bf1);
                }
            }
        }
    }

    const int qrow = qt*128 + w*16;
    float inv0 = 1.f / l0, inv1 = 1.f / l1;
    __half* op = g_ctx + (((size_t)(p*BB+b)*HH + h)*NN + qrow)*HD;
    #pragma unroll
    for (int nf = 0; nf < 8; nf++) {
        *(__half2*)(op + g*64 + nf*8 + 2*t) =
            __floats2half2_rn(o[nf][0]*inv0, o[nf][1]*inv0);
        *(__half2*)(op + (g+8)*64 + nf*8 + 2*t) =
            __floats2half2_rn(o[nf][2]*inv1, o[nf][3]*inv1);
    }
}

// =====================================================================
// Kernel 3: projection GEMM (fp16, warp tile 64x64, 4 warps, K-step 64)
// + bias + q-residual -> f32 out.
// =====================================================================
__global__ __launch_bounds__(128, 2) void proj_gemm_mma(
    const float* __restrict__ bias, float* __restrict__ out)
{
    extern __shared__ __align__(16) unsigned char sp[];
    const int tid = threadIdx.x;
    const int warp = tid >> 5, lane = tid & 31;
    const int wm = warp >> 1, wn = warp & 1;
    const int g = lane >> 2, t = lane & 3;
    const int mt = blockIdx.y;
    const int bn = blockIdx.x * 128;
    const unsigned smb = s2u(sp);

    const __half* actx[8]; unsigned ad[8];
    const __half* bsr[8]; unsigned bd[8];
    #pragma unroll
    for (int i = 0; i < 8; i++) {
        int id = tid + i*128, r = id >> 3, ch = id & 7;
        int gm = mt*128 + r;
        int pp = gm >> 12, b2 = (gm >> 10) & 3, n = gm & 1023;
        unsigned sw = SWZ((unsigned)(r*128 + ch*16));
        actx[i] = g_ctx + (size_t)(pp*BB + b2)*PERSB + (size_t)n*HD + ch*8;
        ad[i]   = smb + sw;
        bsr[i]  = g_wp + (size_t)(bn + r)*CC + ch*8;
        bd[i]   = smb + GTILE2 + sw;
    }
    const unsigned aoffl = (lane & 15)*128 + (lane >> 4)*16;
    const unsigned blinl = ((lane & 7) + ((lane >> 4) & 1)*8)*128 + ((lane >> 3) & 1)*16;

    float acc[4][8][4] = {};

    // K-chunk c = head c: A advance = c*NN*HD, B advance = c*64
    #pragma unroll
    for (int st = 0; st < 2; st++) {
        #pragma unroll
        for (int i = 0; i < 8; i++) {
            cp16(ad[i] + st*GSTG2, actx[i] + (size_t)st*(NN*HD));
            cp16(bd[i] + st*GSTG2, bsr[i] + st*64);
        }
        CPCOMMIT();
    }

    unsigned rdo = 0, wro = 2*GSTG2;
    for (int c = 0; c < 12; c++) {
        if (c < 11) { asm volatile("cp.async.wait_group 1;"); }
        else        { asm volatile("cp.async.wait_group 0;"); }
        __syncthreads();
        if (c < 10) {
            #pragma unroll
            for (int i = 0; i < 8; i++) {
                cp16(ad[i] + wro, actx[i] + (size_t)(c+2)*(NN*HD));
                cp16(bd[i] + wro, bsr[i] + (c+2)*64);
            }
            CPCOMMIT();
            wro += GSTG2; if (wro == 3*GSTG2) wro = 0;
        }
        const unsigned Ab = smb + rdo;
        const unsigned Bb = Ab + GTILE2;
        rdo += GSTG2; if (rdo == 3*GSTG2) rdo = 0;
        #pragma unroll
        for (int kk = 0; kk < 4; kk++) {
            const unsigned sa2 = SWZ(aoffl + kk*32);
            const unsigned sb2 = SWZ(blinl + kk*32);
            unsigned a[4][4], bq[8][2];
            #pragma unroll
            for (int mf = 0; mf < 4; mf++)
                ldsm4(a[mf][0], a[mf][1], a[mf][2], a[mf][3],
                      Ab + sa2 + (wm*64 + mf*16)*128);
            #pragma unroll
            for (int g2 = 0; g2 < 4; g2++) {
                unsigned r0, r1, r2, r3;
                ldsm4(r0, r1, r2, r3, Bb + sb2 + (wn*64 + g2*16)*128);
                bq[2*g2][0] = r0; bq[2*g2][1] = r1;
                bq[2*g2+1][0] = r2; bq[2*g2+1][1] = r3;
            }
            #pragma unroll
            for (int mf = 0; mf < 4; mf++)
                #pragma unroll
                for (int nf = 0; nf < 8; nf++)
                    mma16(acc[mf][nf], a[mf], bq[nf]);
        }
    }

    // epilogue: bias + fp16 flat-q residual -> f32 d_out
    #pragma unroll
    for (int mf = 0; mf < 4; mf++) {
        #pragma unroll
        for (int rr = 0; rr < 2; rr++) {
            int gm = mt*128 + wm*64 + mf*16 + g + rr*8;
            int pp = gm >> 12, b2 = (gm >> 10) & 3, n = gm & 1023;
            const __half* qres = g_q + (size_t)((1-pp)*BB + b2)*PERSB + (size_t)n*CC;
            #pragma unroll
            for (int nf = 0; nf < 8; nf++) {
                int col = bn + wn*64 + nf*8 + 2*t;
                float2 qr = __half22float2(*(const __half2*)(qres + col));
                float2 r;
                r.x = acc[mf][nf][2*rr+0] + __ldg(bias + col)   + qr.x;
                r.y = acc[mf][nf][2*rr+1] + __ldg(bias + col+1) + qr.y;
                *(float2*)(out + (size_t)gm*CC + col) = r;
            }
        }
    }
}

// =====================================================================
extern "C" void kernel_launch(void* const* d_in, const int* in_sizes, int n_in,
                              void* d_out, int out_size) {
    const float* before = (const float*)d_in[0];
    const float* after  = (const float*)d_in[1];
    const float* W_qkv  = (const float*)d_in[2];
    const float* ln_g   = (const float*)d_in[3];
    const float* ln_b   = (const float*)d_in[4];
    const float* W_proj = (const float*)d_in[5];
    const float* b_proj = (const float*)d_in[6];
    float* out = (float*)d_out;

    // 0) convert inputs to fp16
    preround_kernel<<<PR8/256, 256>>>(before, after, W_qkv, W_proj);

    // 1) QKV GEMM + register LN: grid (2304/128, 8192/128), 128 thr
    {
        cudaFuncSetAttribute(qkv_gemm_mma, cudaFuncAttributeMaxDynamicSharedMemorySize, GSMEM2);
        dim3 grid(QKV3/128, MROWS/128);
        qkv_gemm_mma<<<grid, 128, GSMEM2>>>(ln_g, ln_b);
    }
    // 2) Attention: 768 blocks, 256 thr
    {
        cudaFuncSetAttribute(attn_mma, cudaFuncAttributeMaxDynamicSharedMemorySize, ATTN_SMEM);
        attn_mma<<<768, 256, ATTN_SMEM>>>();
    }
    // 3) Projection GEMM: grid (768/128, 8192/128), 128 thr
    {
        cudaFuncSetAttribute(proj_gemm_mma, cudaFuncAttributeMaxDynamicSharedMemorySize, GSMEM2);
        dim3 grid(CC/128, MROWS/128);
        proj_gemm_mma<<<grid, 128, GSMEM2>>>(b_proj, out);
    }
}

// round 13
// speedup vs baseline: 1.1930x; 1.0389x over previous
#include <cuda_runtime.h>
#include <cuda_fp16.h>
#include <math.h>

#define BB 4
#define NN 1024
#define CC 768
#define HH 12
#define HD 64
#define QKV3 (3*CC)          // 2304
#define MROWS (2*BB*NN)      // 8192
#define PERSB (HH*NN*HD)     // 786432 elems per (stream,b)

// -------- scratch (device globals; no allocation) --------
__device__ __half g_q  [2*BB*HH*NN*HD];   // [s][b][h][n][d]
__device__ __half g_k  [2*BB*HH*NN*HD];   // [s][b][h][n][d]
__device__ __half g_v  [2*BB*HH*NN*HD];   // [s][b][h][n][d]
__device__ __half g_ctx[2*BB*HH*NN*HD];   // [p][b][h][n][d]
__device__ __half g_x  [MROWS*CC];        // fp16 [before;after]
__device__ __half g_wq [QKV3*CC];         // fp16 W_qkv
__device__ __half g_wp [CC*CC];           // fp16 W_proj

// -------- helpers --------
__device__ __forceinline__ float ex2f(float x) {
    float y; asm("ex2.approx.ftz.f32 %0, %1;" : "=f"(y) : "f"(x)); return y;
}
__device__ __forceinline__ unsigned pack2(float lo, float hi) {
    unsigned r; asm("cvt.rn.f16x2.f32 %0, %1, %2;" : "=r"(r) : "f"(hi), "f"(lo));
    return r;
}
__device__ __forceinline__ void mma16(float* c, const unsigned* a, const unsigned* b) {
    asm volatile("mma.sync.aligned.m16n8k16.row.col.f32.f16.f16.f32 "
        "{%0,%1,%2,%3}, {%4,%5,%6,%7}, {%8,%9}, {%0,%1,%2,%3};"
        : "+f"(c[0]), "+f"(c[1]), "+f"(c[2]), "+f"(c[3])
        : "r"(a[0]), "r"(a[1]), "r"(a[2]), "r"(a[3]), "r"(b[0]), "r"(b[1]));
}
__device__ __forceinline__ void ldsm4(unsigned& r0, unsigned& r1, unsigned& r2,
                                      unsigned& r3, unsigned addr) {
    asm volatile("ldmatrix.sync.aligned.m8n8.x4.shared.b16 {%0,%1,%2,%3}, [%4];"
        : "=r"(r0), "=r"(r1), "=r"(r2), "=r"(r3) : "r"(addr));
}
__device__ __forceinline__ void ldsm4t(unsigned& r0, unsigned& r1, unsigned& r2,
                                       unsigned& r3, unsigned addr) {
    asm volatile("ldmatrix.sync.aligned.m8n8.x4.trans.shared.b16 {%0,%1,%2,%3}, [%4];"
        : "=r"(r0), "=r"(r1), "=r"(r2), "=r"(r3) : "r"(addr));
}
__device__ __forceinline__ unsigned s2u(const void* p) {
    return (unsigned)__cvta_generic_to_shared(p);
}
__device__ __forceinline__ void cp16(unsigned dst, const void* src) {
    asm volatile("cp.async.cg.shared.global [%0], [%1], 16;" :: "r"(dst), "l"(src));
}
#define CPCOMMIT() asm volatile("cp.async.commit_group;")

// Shared GEMM staging geometry: 128x128 block, K-step 64, 3-stage SW128.
#define SWZ(o)  ((o) ^ (((o) >> 3) & 0x70))
#define GTILE2 16384          // 128 rows x 128 B per operand tile
#define GSTG2  32768          // A + B per stage
#define GSMEM2 (3*GSTG2)      // 98304 B

// =====================================================================
// Kernel 0: convert inputs to fp16 (once). 8 floats per thread.
// =====================================================================
#define XQ8 (MROWS*CC/8)     // 786432
#define WQ8 (QKV3*CC/8)      // 221184
#define PQ8 (CC*CC/8)        // 73728
#define PR8 (XQ8+WQ8+PQ8)    // 1081344 = 4224*256

__global__ __launch_bounds__(256) void preround_kernel(
    const float* __restrict__ before, const float* __restrict__ after,
    const float* __restrict__ Wqkv, const float* __restrict__ Wp)
{
    int i = blockIdx.x*256 + threadIdx.x;
    const float* src; __half* dst;
    if (i < XQ8) {
        src = (i < XQ8/2) ? before + (size_t)i*8 : after + (size_t)(i - XQ8/2)*8;
        dst = g_x + (size_t)i*8;
    } else if (i < XQ8 + WQ8) {
        src = Wqkv + (size_t)(i - XQ8)*8;
        dst = g_wq + (size_t)(i - XQ8)*8;
    } else {
        src = Wp + (size_t)(i - XQ8 - WQ8)*8;
        dst = g_wp + (size_t)(i - XQ8 - WQ8)*8;
    }
    float4 v0 = ((const float4*)src)[0];
    float4 v1 = ((const float4*)src)[1];
    uint4 o;
    o.x = pack2(v0.x, v0.y); o.y = pack2(v0.z, v0.w);
    o.z = pack2(v1.x, v1.y); o.w = pack2(v1.z, v1.w);
    *(uint4*)dst = o;
}

// =====================================================================
// Kernel 1 (r12 winner): QKV GEMM, 128 thr = 4 warps (2m x 2n), warp
// tile 64x64, K-step 64, 3-stage SW128 + REGISTER LayerNorm epilogue.
// =====================================================================
__global__ __launch_bounds__(128, 2) void qkv_gemm_mma(
    const float* __restrict__ ln_g, const float* __restrict__ ln_b)
{
    extern __shared__ __align__(16) unsigned char sq[];
    __shared__ float s_lng[64], s_lnb[64];
    const int tid = threadIdx.x;
    if (tid < 64) { s_lng[tid] = ln_g[tid]; s_lnb[tid] = ln_b[tid]; }

    const int warp = tid >> 5, lane = tid & 31;
    const int wm = warp >> 1, wn = warp & 1;
    const int g = lane >> 2, t = lane & 3;
    const int mt = blockIdx.y;
    const int bn = blockIdx.x * 128;
    const unsigned smb = s2u(sq);

    const __half* asr[8]; unsigned ad[8];
    const __half* bsr[8]; unsigned bd[8];
    #pragma unroll
    for (int i = 0; i < 8; i++) {
        int id = tid + i*128, r = id >> 3, ch = id & 7;
        unsigned sw = SWZ((unsigned)(r*128 + ch*16));
        asr[i] = g_x + (size_t)(mt*128 + r)*CC + ch*8;
        ad[i]  = smb + sw;
        bsr[i] = g_wq + (size_t)(bn + r)*CC + ch*8;
        bd[i]  = smb + GTILE2 + sw;
    }
    const unsigned aoffl = (lane & 15)*128 + (lane >> 4)*16;
    const unsigned blinl = ((lane & 7) + ((lane >> 4) & 1)*8)*128 + ((lane >> 3) & 1)*16;

    float acc[4][8][4] = {};

    #pragma unroll
    for (int st = 0; st < 2; st++) {
        #pragma unroll
        for (int i = 0; i < 8; i++) {
            cp16(ad[i] + st*GSTG2, asr[i] + st*64);
            cp16(bd[i] + st*GSTG2, bsr[i] + st*64);
        }
        CPCOMMIT();
    }

    unsigned rdo = 0, wro = 2*GSTG2;
    for (int c = 0; c < 12; c++) {
        if (c < 11) { asm volatile("cp.async.wait_group 1;"); }
        else        { asm volatile("cp.async.wait_group 0;"); }
        __syncthreads();
        if (c < 10) {
            #pragma unroll
            for (int i = 0; i < 8; i++) {
                cp16(ad[i] + wro, asr[i] + (c+2)*64);
                cp16(bd[i] + wro, bsr[i] + (c+2)*64);
            }
            CPCOMMIT();
            wro += GSTG2; if (wro == 3*GSTG2) wro = 0;
        }
        const unsigned Ab = smb + rdo;
        const unsigned Bb = Ab + GTILE2;
        rdo += GSTG2; if (rdo == 3*GSTG2) rdo = 0;
        #pragma unroll
        for (int kk = 0; kk < 4; kk++) {
            const unsigned sa2 = SWZ(aoffl + kk*32);
            const unsigned sb2 = SWZ(blinl + kk*32);
            unsigned a[4][4], bq[8][2];
            #pragma unroll
            for (int mf = 0; mf < 4; mf++)
                ldsm4(a[mf][0], a[mf][1], a[mf][2], a[mf][3],
                      Ab + sa2 + (wm*64 + mf*16)*128);
            #pragma unroll
            for (int g2 = 0; g2 < 4; g2++) {
                unsigned r0, r1, r2, r3;
                ldsm4(r0, r1, r2, r3, Bb + sb2 + (wn*64 + g2*16)*128);
                bq[2*g2][0] = r0; bq[2*g2][1] = r1;
                bq[2*g2+1][0] = r2; bq[2*g2+1][1] = r3;
            }
            #pragma unroll
            for (int mf = 0; mf < 4; mf++)
                #pragma unroll
                for (int nf = 0; nf < 8; nf++)
                    mma16(acc[mf][nf], a[mf], bq[nf]);
        }
    }

    // register-resident LayerNorm epilogue (wn column == one 64-wide head)
    const int cb = bn + wn*64;
    const int tq = cb / CC;                 // 0=q,1=k,2=v
    const int h  = (cb % CC) >> 6;
    const int gm0 = mt*128;
    const int s = gm0 >> 12, b = (gm0 >> 10) & 3;
    __half* dbase = (tq == 0 ? g_q : tq == 1 ? g_k : g_v)
                  + ((((size_t)(s*BB+b)*HH + h)*NN) + (gm0 & 1023))*HD;

    #pragma unroll
    for (int mf = 0; mf < 4; mf++) {
        float sum0 = 0.f, sq0 = 0.f, sum1 = 0.f, sq1 = 0.f;
        #pragma unroll
        for (int nf = 0; nf < 8; nf++) {
            float a0 = acc[mf][nf][0], a1 = acc[mf][nf][1];
            float a2 = acc[mf][nf][2], a3 = acc[mf][nf][3];
            sum0 += a0 + a1; sq0 += a0*a0 + a1*a1;
            sum1 += a2 + a3; sq1 += a2*a2 + a3*a3;
        }
        sum0 += __shfl_xor_sync(0xffffffffu, sum0, 1);
        sum0 += __shfl_xor_sync(0xffffffffu, sum0, 2);
        sq0  += __shfl_xor_sync(0xffffffffu, sq0, 1);
        sq0  += __shfl_xor_sync(0xffffffffu, sq0, 2);
        sum1 += __shfl_xor_sync(0xffffffffu, sum1, 1);
        sum1 += __shfl_xor_sync(0xffffffffu, sum1, 2);
        sq1  += __shfl_xor_sync(0xffffffffu, sq1, 1);
        sq1  += __shfl_xor_sync(0xffffffffu, sq1, 2);
        float mu0 = sum0 * (1.f/64.f);
        float rs0 = rsqrtf(sq0 * (1.f/64.f) - mu0*mu0 + 1e-5f);
        float mu1 = sum1 * (1.f/64.f);
        float rs1 = rsqrtf(sq1 * (1.f/64.f) - mu1*mu1 + 1e-5f);

        int r0 = wm*64 + mf*16 + g;
        __half* d0 = dbase + (size_t)r0*HD;
        __half* d1 = dbase + (size_t)(r0+8)*HD;
        #pragma unroll
        for (int nf = 0; nf < 8; nf++) {
            int col = nf*8 + 2*t;
            float g0 = s_lng[col], g1 = s_lng[col+1];
            float b0 = s_lnb[col], b1 = s_lnb[col+1];
            *(__half2*)(d0 + col) = __floats2half2_rn(
                (acc[mf][nf][0]-mu0)*rs0*g0 + b0,
                (acc[mf][nf][1]-mu0)*rs0*g1 + b1);
            *(__half2*)(d1 + col) = __floats2half2_rn(
                (acc[mf][nf][2]-mu1)*rs1*g0 + b0,
                (acc[mf][nf][3]-mu1)*rs1*g1 + b1);
        }
    }
}

// =====================================================================
// Kernel 2 (r10 form): attention, fp16 m16n8k16, 256 thr = 8 warps,
// q-tile 128, kv-tile 128, 2 CTAs/SM, Q in regs, P packed from accums.
// =====================================================================
#define ARS 144               // 64 halves + 8 pad = 144 B per row
#define QB  0
#define KB0 (128*ARS)         // 18432
#define VB0 (KB0 + 2*128*ARS) // 55296
#define ATTN_SMEM (VB0 + 2*128*ARS)   // 92160

__global__ __launch_bounds__(256, 2) void attn_mma() {
    extern __shared__ __align__(16) unsigned char sa[];
    const unsigned smb = s2u(sa);

    const int bx = blockIdx.x;
    const int qt = bx & 7;
    const int h  = (bx >> 3) % 12;
    const int b  = (bx / 96) & 3;
    const int p  = bx / 384;
    const int qs = 1 - p, kvs = p;

    const __half* qptr = g_q + (((size_t)(qs*BB+b)*HH + h)*NN + qt*128)*HD;
    const __half* kptr = g_k + (((size_t)(kvs*BB+b)*HH + h)*NN)*HD;
    const __half* vptr = g_v + (((size_t)(kvs*BB+b)*HH + h)*NN)*HD;

    const int tid = threadIdx.x, w = tid >> 5, lane = tid & 31;
    const int g = lane >> 2, t = lane & 3;

    const unsigned aoffA = ((lane & 15)*ARS + (lane >> 4)*16);
    const unsigned boffK = (((lane & 7) + ((lane >> 4) & 1)*8)*ARS + ((lane >> 3) & 1)*16);
    const unsigned boffV = (((lane & 7) + ((lane >> 3) & 1)*8)*ARS + (lane >> 4)*16);

    int srow[4], sch[4];
    #pragma unroll
    for (int i = 0; i < 4; i++) {
        int id = tid + i*256; srow[i] = id >> 3; sch[i] = id & 7;
    }

    #pragma unroll
    for (int i = 0; i < 4; i++) {
        cp16(smb + KB0 + srow[i]*ARS + sch[i]*16, kptr + srow[i]*64 + sch[i]*8);
        cp16(smb + VB0 + srow[i]*ARS + sch[i]*16, vptr + srow[i]*64 + sch[i]*8);
    }
    CPCOMMIT();

    #pragma unroll
    for (int i = 0; i < 4; i++) {
        int id = tid + i*256, row = id >> 3, ch = id & 7;
        *(uint4*)(sa + QB + row*ARS + ch*16) = *(const uint4*)(qptr + row*64 + ch*8);
    }
    __syncthreads();
    unsigned q[4][4];
    #pragma unroll
    for (int kk = 0; kk < 4; kk++)
        ldsm4(q[kk][0], q[kk][1], q[kk][2], q[kk][3],
              smb + QB + (w*16)*ARS + kk*32 + aoffA);

    const float SC = 0.125f * 1.44269504088896f;   // scale * log2(e)
    float o[8][4] = {};
    float m0 = -1e30f, m1 = -1e30f, l0 = 0.f, l1 = 0.f;

    for (int kc = 0; kc < 8; kc++) {
        __syncthreads();
        if (kc < 7) {
            const __half* kp = kptr + (kc+1)*128*64;
            const __half* vp = vptr + (kc+1)*128*64;
            const unsigned kb = smb + KB0 + ((kc+1)&1)*(128*ARS);
            const unsigned vb = smb + VB0 + ((kc+1)&1)*(128*ARS);
            #pragma unroll
            for (int i = 0; i < 4; i++) {
                cp16(kb + srow[i]*ARS + sch[i]*16, kp + srow[i]*64 + sch[i]*8);
                cp16(vb + srow[i]*ARS + sch[i]*16, vp + srow[i]*64 + sch[i]*8);
            }
            CPCOMMIT();
            asm volatile("cp.async.wait_group 1;");
        } else {
            asm volatile("cp.async.wait_group 0;");
        }
        __syncthreads();

        const unsigned Kb = smb + KB0 + (kc&1)*(128*ARS);
        const unsigned Vb = smb + VB0 + (kc&1)*(128*ARS);

        #pragma unroll
        for (int half = 0; half < 2; half++) {
            const unsigned Kh = Kb + half*64*ARS;
            const unsigned Vh = Vb + half*64*ARS;

            float s[8][4] = {};
            #pragma unroll
            for (int kk = 0; kk < 4; kk++) {
                #pragma unroll
                for (int j2 = 0; j2 < 4; j2++) {
                    unsigned r0, r1, r2, r3;
                    ldsm4(r0, r1, r2, r3, Kh + (j2*16)*ARS + kk*32 + boffK);
                    unsigned bf0[2] = {r0, r1}, bf1[2] = {r2, r3};
                    mma16(s[2*j2], q[kk], bf0);
                    mma16(s[2*j2+1], q[kk], bf1);
                }
            }

            float mx0 = -1e30f, mx1 = -1e30f;
            #pragma unroll
            for (int nf = 0; nf < 8; nf++) {
                #pragma unroll
                for (int j = 0; j < 4; j++) s[nf][j] *= SC;
                mx0 = fmaxf(mx0, fmaxf(s[nf][0], s[nf][1]));
                mx1 = fmaxf(mx1, fmaxf(s[nf][2], s[nf][3]));
            }
            mx0 = fmaxf(mx0, __shfl_xor_sync(0xffffffffu, mx0, 1));
            mx0 = fmaxf(mx0, __shfl_xor_sync(0xffffffffu, mx0, 2));
            mx1 = fmaxf(mx1, __shfl_xor_sync(0xffffffffu, mx1, 1));
            mx1 = fmaxf(mx1, __shfl_xor_sync(0xffffffffu, mx1, 2));
            float M0 = fmaxf(m0, mx0), M1 = fmaxf(m1, mx1);
            float c0 = ex2f(m0 - M0), c1 = ex2f(m1 - M1);
            float ls0 = 0.f, ls1 = 0.f;
            #pragma unroll
            for (int nf = 0; nf < 8; nf++) {
                s[nf][0] = ex2f(s[nf][0] - M0);
                s[nf][1] = ex2f(s[nf][1] - M0);
                s[nf][2] = ex2f(s[nf][2] - M1);
                s[nf][3] = ex2f(s[nf][3] - M1);
                ls0 += s[nf][0] + s[nf][1];
                ls1 += s[nf][2] + s[nf][3];
            }
            ls0 += __shfl_xor_sync(0xffffffffu, ls0, 1);
            ls0 += __shfl_xor_sync(0xffffffffu, ls0, 2);
            ls1 += __shfl_xor_sync(0xffffffffu, ls1, 1);
            ls1 += __shfl_xor_sync(0xffffffffu, ls1, 2);
            l0 = l0*c0 + ls0; l1 = l1*c1 + ls1;
            m0 = M0; m1 = M1;
            #pragma unroll
            for (int nf = 0; nf < 8; nf++) {
                o[nf][0] *= c0; o[nf][1] *= c0; o[nf][2] *= c1; o[nf][3] *= c1;
            }

            #pragma unroll
            for (int kc2 = 0; kc2 < 4; kc2++) {
                unsigned a[4];
                a[0] = pack2(s[2*kc2][0],   s[2*kc2][1]);
                a[1] = pack2(s[2*kc2][2],   s[2*kc2][3]);
                a[2] = pack2(s[2*kc2+1][0], s[2*kc2+1][1]);
                a[3] = pack2(s[2*kc2+1][2], s[2*kc2+1][3]);
                #pragma unroll
                for (int j = 0; j < 4; j++) {
                    unsigned r0, r1, r2, r3;
                    ldsm4t(r0, r1, r2, r3, Vh + (kc2*16)*ARS + j*32 + boffV);
                    unsigned bf0[2] = {r0, r1}, bf1[2] = {r2, r3};
                    mma16(o[2*j], a, bf0);
                    mma16(o[2*j+1], a, bf1);
                }
            }
        }
    }

    const int qrow = qt*128 + w*16;
    float inv0 = 1.f / l0, inv1 = 1.f / l1;
    __half* op = g_ctx + (((size_t)(p*BB+b)*HH + h)*NN + qrow)*HD;
    #pragma unroll
    for (int nf = 0; nf < 8; nf++) {
        *(__half2*)(op + g*64 + nf*8 + 2*t) =
            __floats2half2_rn(o[nf][0]*inv0, o[nf][1]*inv0);
        *(__half2*)(op + (g+8)*64 + nf*8 + 2*t) =
            __floats2half2_rn(o[nf][2]*inv1, o[nf][3]*inv1);
    }
}

// =====================================================================
// Kernel 3 (r10 winner): projection GEMM, 256 thr = 8 warps (2m x 4n),
// warp tile 64x32, K-step 64 = one head, 3-stage SW128.
// + bias + q-residual -> f32 out.
// =====================================================================
__global__ __launch_bounds__(256, 2) void proj_gemm_mma(
    const float* __restrict__ bias, float* __restrict__ out)
{
    extern __shared__ __align__(16) unsigned char sp[];
    const int tid = threadIdx.x;
    const int warp = tid >> 5, lane = tid & 31;
    const int wm = warp >> 2, wn = warp & 3;
    const int g = lane >> 2, t = lane & 3;
    const int mt = blockIdx.y;
    const int bn = blockIdx.x * 128;
    const unsigned smb = s2u(sp);

    const __half* actx[4]; unsigned ad[4];
    const __half* bsr[4]; unsigned bd[4];
    #pragma unroll
    for (int i = 0; i < 4; i++) {
        int id = tid + i*256, r = id >> 3, ch = id & 7;
        int gm = mt*128 + r;
        int pp = gm >> 12, b2 = (gm >> 10) & 3, n = gm & 1023;
        unsigned sw = SWZ((unsigned)(r*128 + ch*16));
        actx[i] = g_ctx + (size_t)(pp*BB + b2)*PERSB + (size_t)n*HD + ch*8;
        ad[i]   = smb + sw;
        bsr[i]  = g_wp + (size_t)(bn + r)*CC + ch*8;
        bd[i]   = smb + GTILE2 + sw;
    }
    const unsigned aoffl = (lane & 15)*128 + (lane >> 4)*16;
    const unsigned blinl = ((lane & 7) + ((lane >> 4) & 1)*8)*128 + ((lane >> 3) & 1)*16;

    float acc[4][4][4] = {};

    // K-chunk c = head c: A advance = c*NN*HD, B advance = c*64
    #pragma unroll
    for (int st = 0; st < 2; st++) {
        #pragma unroll
        for (int i = 0; i < 4; i++) {
            cp16(ad[i] + st*GSTG2, actx[i] + (size_t)st*(NN*HD));
            cp16(bd[i] + st*GSTG2, bsr[i] + st*64);
        }
        CPCOMMIT();
    }

    unsigned rdo = 0, wro = 2*GSTG2;
    for (int c = 0; c < 12; c++) {
        if (c < 11) { asm volatile("cp.async.wait_group 1;"); }
        else        { asm volatile("cp.async.wait_group 0;"); }
        __syncthreads();
        if (c < 10) {
            #pragma unroll
            for (int i = 0; i < 4; i++) {
                cp16(ad[i] + wro, actx[i] + (size_t)(c+2)*(NN*HD));
                cp16(bd[i] + wro, bsr[i] + (c+2)*64);
            }
            CPCOMMIT();
            wro += GSTG2; if (wro == 3*GSTG2) wro = 0;
        }
        const unsigned Ab = smb + rdo;
        const unsigned Bb = Ab + GTILE2;
        rdo += GSTG2; if (rdo == 3*GSTG2) rdo = 0;
        #pragma unroll
        for (int kk = 0; kk < 4; kk++) {
            const unsigned sa2 = SWZ(aoffl + kk*32);
            const unsigned sb2 = SWZ(blinl + kk*32);
            unsigned a[4][4], bq[4][2];
            #pragma unroll
            for (int mf = 0; mf < 4; mf++)
                ldsm4(a[mf][0], a[mf][1], a[mf][2], a[mf][3],
                      Ab + sa2 + (wm*64 + mf*16)*128);
            #pragma unroll
            for (int g2 = 0; g2 < 2; g2++) {
                unsigned r0, r1, r2, r3;
                ldsm4(r0, r1, r2, r3, Bb + sb2 + (wn*32 + g2*16)*128);
                bq[2*g2][0] = r0; bq[2*g2][1] = r1;
                bq[2*g2+1][0] = r2; bq[2*g2+1][1] = r3;
            }
            #pragma unroll
            for (int mf = 0; mf < 4; mf++)
                #pragma unroll
                for (int nf = 0; nf < 4; nf++)
                    mma16(acc[mf][nf], a[mf], bq[nf]);
        }
    }

    // epilogue: bias + fp16 flat-q residual -> f32 d_out
    #pragma unroll
    for (int mf = 0; mf < 4; mf++) {
        #pragma unroll
        for (int rr = 0; rr < 2; rr++) {
            int gm = mt*128 + wm*64 + mf*16 + g + rr*8;
            int pp = gm >> 12, b2 = (gm >> 10) & 3, n = gm & 1023;
            const __half* qres = g_q + (size_t)((1-pp)*BB + b2)*PERSB + (size_t)n*CC;
            #pragma unroll
            for (int nf = 0; nf < 4; nf++) {
                int col = bn + wn*32 + nf*8 + 2*t;
                float2 qr = __half22float2(*(const __half2*)(qres + col));
                float2 r;
                r.x = acc[mf][nf][2*rr+0] + __ldg(bias + col)   + qr.x;
                r.y = acc[mf][nf][2*rr+1] + __ldg(bias + col+1) + qr.y;
                *(float2*)(out + (size_t)gm*CC + col) = r;
            }
        }
    }
}

// =====================================================================
extern "C" void kernel_launch(void* const* d_in, const int* in_sizes, int n_in,
                              void* d_out, int out_size) {
    const float* before = (const float*)d_in[0];
    const float* after  = (const float*)d_in[1];
    const float* W_qkv  = (const float*)d_in[2];
    const float* ln_g   = (const float*)d_in[3];
    const float* ln_b   = (const float*)d_in[4];
    const float* W_proj = (const float*)d_in[5];
    const float* b_proj = (const float*)d_in[6];
    float* out = (float*)d_out;

    // 0) convert inputs to fp16
    preround_kernel<<<PR8/256, 256>>>(before, after, W_qkv, W_proj);

    // 1) QKV GEMM + register LN: grid (2304/128, 8192/128), 128 thr
    {
        cudaFuncSetAttribute(qkv_gemm_mma, cudaFuncAttributeMaxDynamicSharedMemorySize, GSMEM2);
        dim3 grid(QKV3/128, MROWS/128);
        qkv_gemm_mma<<<grid, 128, GSMEM2>>>(ln_g, ln_b);
    }
    // 2) Attention: 768 blocks, 256 thr
    {
        cudaFuncSetAttribute(attn_mma, cudaFuncAttributeMaxDynamicSharedMemorySize, ATTN_SMEM);
        attn_mma<<<768, 256, ATTN_SMEM>>>();
    }
    // 3) Projection GEMM: grid (768/128, 8192/128), 256 thr
    {
        cudaFuncSetAttribute(proj_gemm_mma, cudaFuncAttributeMaxDynamicSharedMemorySize, GSMEM2);
        dim3 grid(CC/128, MROWS/128);
        proj_gemm_mma<<<grid, 256, GSMEM2>>>(b_proj, out);
    }
}

// round 14
// speedup vs baseline: 1.2229x; 1.0250x over previous
#include <cuda_runtime.h>
#include <cuda_fp16.h>
#include <math.h>

#define BB 4
#define NN 1024
#define CC 768
#define HH 12
#define HD 64
#define QKV3 (3*CC)          // 2304
#define MROWS (2*BB*NN)      // 8192
#define PERSB (HH*NN*HD)     // 786432 elems per (stream,b)

// -------- scratch (device globals; no allocation) --------
__device__ __half g_q  [2*BB*HH*NN*HD];   // [s][b][h][n][d]
__device__ __half g_k  [2*BB*HH*NN*HD];   // [s][b][h][n][d]
__device__ __half g_v  [2*BB*HH*NN*HD];   // [s][b][h][n][d]
__device__ __half g_ctx[2*BB*HH*NN*HD];   // [p][b][h][n][d]
__device__ __half g_x  [MROWS*CC];        // fp16 [before;after]
__device__ __half g_wq [QKV3*CC];         // fp16 W_qkv
__device__ __half g_wp [CC*CC];           // fp16 W_proj

// -------- helpers --------
__device__ __forceinline__ float ex2f(float x) {
    float y; asm("ex2.approx.ftz.f32 %0, %1;" : "=f"(y) : "f"(x)); return y;
}
__device__ __forceinline__ unsigned pack2(float lo, float hi) {
    unsigned r; asm("cvt.rn.f16x2.f32 %0, %1, %2;" : "=r"(r) : "f"(hi), "f"(lo));
    return r;
}
__device__ __forceinline__ void mma16(float* c, const unsigned* a, const unsigned* b) {
    asm volatile("mma.sync.aligned.m16n8k16.row.col.f32.f16.f16.f32 "
        "{%0,%1,%2,%3}, {%4,%5,%6,%7}, {%8,%9}, {%0,%1,%2,%3};"
        : "+f"(c[0]), "+f"(c[1]), "+f"(c[2]), "+f"(c[3])
        : "r"(a[0]), "r"(a[1]), "r"(a[2]), "r"(a[3]), "r"(b[0]), "r"(b[1]));
}
__device__ __forceinline__ void ldsm4(unsigned& r0, unsigned& r1, unsigned& r2,
                                      unsigned& r3, unsigned addr) {
    asm volatile("ldmatrix.sync.aligned.m8n8.x4.shared.b16 {%0,%1,%2,%3}, [%4];"
        : "=r"(r0), "=r"(r1), "=r"(r2), "=r"(r3) : "r"(addr));
}
__device__ __forceinline__ void ldsm4t(unsigned& r0, unsigned& r1, unsigned& r2,
                                       unsigned& r3, unsigned addr) {
    asm volatile("ldmatrix.sync.aligned.m8n8.x4.trans.shared.b16 {%0,%1,%2,%3}, [%4];"
        : "=r"(r0), "=r"(r1), "=r"(r2), "=r"(r3) : "r"(addr));
}
__device__ __forceinline__ unsigned s2u(const void* p) {
    return (unsigned)__cvta_generic_to_shared(p);
}
__device__ __forceinline__ void cp16(unsigned dst, const void* src) {
    asm volatile("cp.async.cg.shared.global [%0], [%1], 16;" :: "r"(dst), "l"(src));
}
#define CPCOMMIT() asm volatile("cp.async.commit_group;")

// Shared GEMM staging geometry: 128x128 block, K-step 64, 3-stage SW128.
#define SWZ(o)  ((o) ^ (((o) >> 3) & 0x70))
#define GTILE2 16384          // 128 rows x 128 B per operand tile
#define GSTG2  32768          // A + B per stage
#define GSMEM2 (3*GSTG2)      // 98304 B

// =====================================================================
// Kernel 0: convert inputs to fp16 (once). 8 floats per thread.
// =====================================================================
#define XQ8 (MROWS*CC/8)     // 786432
#define WQ8 (QKV3*CC/8)      // 221184
#define PQ8 (CC*CC/8)        // 73728
#define PR8 (XQ8+WQ8+PQ8)    // 1081344 = 4224*256

__global__ __launch_bounds__(256) void preround_kernel(
    const float* __restrict__ before, const float* __restrict__ after,
    const float* __restrict__ Wqkv, const float* __restrict__ Wp)
{
    int i = blockIdx.x*256 + threadIdx.x;
    const float* src; __half* dst;
    if (i < XQ8) {
        src = (i < XQ8/2) ? before + (size_t)i*8 : after + (size_t)(i - XQ8/2)*8;
        dst = g_x + (size_t)i*8;
    } else if (i < XQ8 + WQ8) {
        src = Wqkv + (size_t)(i - XQ8)*8;
        dst = g_wq + (size_t)(i - XQ8)*8;
    } else {
        src = Wp + (size_t)(i - XQ8 - WQ8)*8;
        dst = g_wp + (size_t)(i - XQ8 - WQ8)*8;
    }
    float4 v0 = ((const float4*)src)[0];
    float4 v1 = ((const float4*)src)[1];
    uint4 o;
    o.x = pack2(v0.x, v0.y); o.y = pack2(v0.z, v0.w);
    o.z = pack2(v1.x, v1.y); o.w = pack2(v1.z, v1.w);
    *(uint4*)dst = o;
}

// =====================================================================
// Kernel 1 (r12/r13 winner): QKV GEMM, 128 thr = 4 warps (2m x 2n), warp
// tile 64x64, K-step 64, 3-stage SW128 + REGISTER LayerNorm epilogue.
// =====================================================================
__global__ __launch_bounds__(128, 2) void qkv_gemm_mma(
    const float* __restrict__ ln_g, const float* __restrict__ ln_b)
{
    extern __shared__ __align__(16) unsigned char sq[];
    __shared__ float s_lng[64], s_lnb[64];
    const int tid = threadIdx.x;
    if (tid < 64) { s_lng[tid] = ln_g[tid]; s_lnb[tid] = ln_b[tid]; }

    const int warp = tid >> 5, lane = tid & 31;
    const int wm = warp >> 1, wn = warp & 1;
    const int g = lane >> 2, t = lane & 3;
    const int mt = blockIdx.y;
    const int bn = blockIdx.x * 128;
    const unsigned smb = s2u(sq);

    const __half* asr[8]; unsigned ad[8];
    const __half* bsr[8]; unsigned bd[8];
    #pragma unroll
    for (int i = 0; i < 8; i++) {
        int id = tid + i*128, r = id >> 3, ch = id & 7;
        unsigned sw = SWZ((unsigned)(r*128 + ch*16));
        asr[i] = g_x + (size_t)(mt*128 + r)*CC + ch*8;
        ad[i]  = smb + sw;
        bsr[i] = g_wq + (size_t)(bn + r)*CC + ch*8;
        bd[i]  = smb + GTILE2 + sw;
    }
    const unsigned aoffl = (lane & 15)*128 + (lane >> 4)*16;
    const unsigned blinl = ((lane & 7) + ((lane >> 4) & 1)*8)*128 + ((lane >> 3) & 1)*16;

    float acc[4][8][4] = {};

    #pragma unroll
    for (int st = 0; st < 2; st++) {
        #pragma unroll
        for (int i = 0; i < 8; i++) {
            cp16(ad[i] + st*GSTG2, asr[i] + st*64);
            cp16(bd[i] + st*GSTG2, bsr[i] + st*64);
        }
        CPCOMMIT();
    }

    unsigned rdo = 0, wro = 2*GSTG2;
    for (int c = 0; c < 12; c++) {
        if (c < 11) { asm volatile("cp.async.wait_group 1;"); }
        else        { asm volatile("cp.async.wait_group 0;"); }
        __syncthreads();
        if (c < 10) {
            #pragma unroll
            for (int i = 0; i < 8; i++) {
                cp16(ad[i] + wro, asr[i] + (c+2)*64);
                cp16(bd[i] + wro, bsr[i] + (c+2)*64);
            }
            CPCOMMIT();
            wro += GSTG2; if (wro == 3*GSTG2) wro = 0;
        }
        const unsigned Ab = smb + rdo;
        const unsigned Bb = Ab + GTILE2;
        rdo += GSTG2; if (rdo == 3*GSTG2) rdo = 0;
        #pragma unroll
        for (int kk = 0; kk < 4; kk++) {
            const unsigned sa2 = SWZ(aoffl + kk*32);
            const unsigned sb2 = SWZ(blinl + kk*32);
            unsigned a[4][4], bq[8][2];
            #pragma unroll
            for (int mf = 0; mf < 4; mf++)
                ldsm4(a[mf][0], a[mf][1], a[mf][2], a[mf][3],
                      Ab + sa2 + (wm*64 + mf*16)*128);
            #pragma unroll
            for (int g2 = 0; g2 < 4; g2++) {
                unsigned r0, r1, r2, r3;
                ldsm4(r0, r1, r2, r3, Bb + sb2 + (wn*64 + g2*16)*128);
                bq[2*g2][0] = r0; bq[2*g2][1] = r1;
                bq[2*g2+1][0] = r2; bq[2*g2+1][1] = r3;
            }
            #pragma unroll
            for (int mf = 0; mf < 4; mf++)
                #pragma unroll
                for (int nf = 0; nf < 8; nf++)
                    mma16(acc[mf][nf], a[mf], bq[nf]);
        }
    }

    // register-resident LayerNorm epilogue (wn column == one 64-wide head)
    const int cb = bn + wn*64;
    const int tq = cb / CC;                 // 0=q,1=k,2=v
    const int h  = (cb % CC) >> 6;
    const int gm0 = mt*128;
    const int s = gm0 >> 12, b = (gm0 >> 10) & 3;
    __half* dbase = (tq == 0 ? g_q : tq == 1 ? g_k : g_v)
                  + ((((size_t)(s*BB+b)*HH + h)*NN) + (gm0 & 1023))*HD;

    #pragma unroll
    for (int mf = 0; mf < 4; mf++) {
        float sum0 = 0.f, sq0 = 0.f, sum1 = 0.f, sq1 = 0.f;
        #pragma unroll
        for (int nf = 0; nf < 8; nf++) {
            float a0 = acc[mf][nf][0], a1 = acc[mf][nf][1];
            float a2 = acc[mf][nf][2], a3 = acc[mf][nf][3];
            sum0 += a0 + a1; sq0 += a0*a0 + a1*a1;
            sum1 += a2 + a3; sq1 += a2*a2 + a3*a3;
        }
        sum0 += __shfl_xor_sync(0xffffffffu, sum0, 1);
        sum0 += __shfl_xor_sync(0xffffffffu, sum0, 2);
        sq0  += __shfl_xor_sync(0xffffffffu, sq0, 1);
        sq0  += __shfl_xor_sync(0xffffffffu, sq0, 2);
        sum1 += __shfl_xor_sync(0xffffffffu, sum1, 1);
        sum1 += __shfl_xor_sync(0xffffffffu, sum1, 2);
        sq1  += __shfl_xor_sync(0xffffffffu, sq1, 1);
        sq1  += __shfl_xor_sync(0xffffffffu, sq1, 2);
        float mu0 = sum0 * (1.f/64.f);
        float rs0 = rsqrtf(sq0 * (1.f/64.f) - mu0*mu0 + 1e-5f);
        float mu1 = sum1 * (1.f/64.f);
        float rs1 = rsqrtf(sq1 * (1.f/64.f) - mu1*mu1 + 1e-5f);

        int r0 = wm*64 + mf*16 + g;
        __half* d0 = dbase + (size_t)r0*HD;
        __half* d1 = dbase + (size_t)(r0+8)*HD;
        #pragma unroll
        for (int nf = 0; nf < 8; nf++) {
            int col = nf*8 + 2*t;
            float g0 = s_lng[col], g1 = s_lng[col+1];
            float b0 = s_lnb[col], b1 = s_lnb[col+1];
            *(__half2*)(d0 + col) = __floats2half2_rn(
                (acc[mf][nf][0]-mu0)*rs0*g0 + b0,
                (acc[mf][nf][1]-mu0)*rs0*g1 + b1);
            *(__half2*)(d1 + col) = __floats2half2_rn(
                (acc[mf][nf][2]-mu1)*rs1*g0 + b0,
                (acc[mf][nf][3]-mu1)*rs1*g1 + b1);
        }
    }
}

// =====================================================================
// Kernel 2 (NEW): attention, 128 thr = 4 warps, warp owns 32 q-rows
// (2 m-frags; K/V fragments shared across m-frags -> ldsm:mma = 1:4).
// q-tile 128, kv-tile 128, 2 CTAs/SM, Q in regs, P packed from accums.
// =====================================================================
#define ARS 144               // 64 halves + 8 pad = 144 B per row
#define QB  0
#define KB0 (128*ARS)         // 18432
#define VB0 (KB0 + 2*128*ARS) // 55296
#define ATTN_SMEM (VB0 + 2*128*ARS)   // 92160

__global__ __launch_bounds__(128, 2) void attn_mma() {
    extern __shared__ __align__(16) unsigned char sa[];
    const unsigned smb = s2u(sa);

    const int bx = blockIdx.x;
    const int qt = bx & 7;
    const int h  = (bx >> 3) % 12;
    const int b  = (bx / 96) & 3;
    const int p  = bx / 384;
    const int qs = 1 - p, kvs = p;

    const __half* qptr = g_q + (((size_t)(qs*BB+b)*HH + h)*NN + qt*128)*HD;
    const __half* kptr = g_k + (((size_t)(kvs*BB+b)*HH + h)*NN)*HD;
    const __half* vptr = g_v + (((size_t)(kvs*BB+b)*HH + h)*NN)*HD;

    const int tid = threadIdx.x, w = tid >> 5, lane = tid & 31;
    const int g = lane >> 2, t = lane & 3;

    const unsigned aoffA = ((lane & 15)*ARS + (lane >> 4)*16);
    const unsigned boffK = (((lane & 7) + ((lane >> 4) & 1)*8)*ARS + ((lane >> 3) & 1)*16);
    const unsigned boffV = (((lane & 7) + ((lane >> 3) & 1)*8)*ARS + (lane >> 4)*16);

    // staging coords: K/V 128 rows x 8 chunks each; 8 K + 8 V cp16 per thread
    int srow[8], sch[8];
    #pragma unroll
    for (int i = 0; i < 8; i++) {
        int id = tid + i*128; srow[i] = id >> 3; sch[i] = id & 7;
    }

    // prefetch kc=0 into buffer 0
    #pragma unroll
    for (int i = 0; i < 8; i++) {
        cp16(smb + KB0 + srow[i]*ARS + sch[i]*16, kptr + srow[i]*64 + sch[i]*8);
        cp16(smb + VB0 + srow[i]*ARS + sch[i]*16, vptr + srow[i]*64 + sch[i]*8);
    }
    CPCOMMIT();

    // stage Q (128x64 fp16) and hoist both m-frags to registers
    #pragma unroll
    for (int i = 0; i < 8; i++) {
        int id = tid + i*128, row = id >> 3, ch = id & 7;
        *(uint4*)(sa + QB + row*ARS + ch*16) = *(const uint4*)(qptr + row*64 + ch*8);
    }
    __syncthreads();
    unsigned q[2][4][4];
    #pragma unroll
    for (int mf = 0; mf < 2; mf++)
        #pragma unroll
        for (int kk = 0; kk < 4; kk++)
            ldsm4(q[mf][kk][0], q[mf][kk][1], q[mf][kk][2], q[mf][kk][3],
                  smb + QB + (w*32 + mf*16)*ARS + kk*32 + aoffA);

    const float SC = 0.125f * 1.44269504088896f;   // scale * log2(e)
    float o[2][8][4] = {};
    float mm[2][2] = {{-1e30f,-1e30f},{-1e30f,-1e30f}};
    float ll[2][2] = {{0.f,0.f},{0.f,0.f}};

    for (int kc = 0; kc < 8; kc++) {
        __syncthreads();
        if (kc < 7) {
            const __half* kp = kptr + (kc+1)*128*64;
            const __half* vp = vptr + (kc+1)*128*64;
            const unsigned kb = smb + KB0 + ((kc+1)&1)*(128*ARS);
            const unsigned vb = smb + VB0 + ((kc+1)&1)*(128*ARS);
            #pragma unroll
            for (int i = 0; i < 8; i++) {
                cp16(kb + srow[i]*ARS + sch[i]*16, kp + srow[i]*64 + sch[i]*8);
                cp16(vb + srow[i]*ARS + sch[i]*16, vp + srow[i]*64 + sch[i]*8);
            }
            CPCOMMIT();
            asm volatile("cp.async.wait_group 1;");
        } else {
            asm volatile("cp.async.wait_group 0;");
        }
        __syncthreads();

        const unsigned Kb = smb + KB0 + (kc&1)*(128*ARS);
        const unsigned Vb = smb + VB0 + (kc&1)*(128*ARS);

        #pragma unroll
        for (int half = 0; half < 2; half++) {
            const unsigned Kh = Kb + half*64*ARS;
            const unsigned Vh = Vb + half*64*ARS;

            // S = Q K^T over 64 kv columns, both m-frags sharing K frags
            float s[2][8][4] = {};
            #pragma unroll
            for (int kk = 0; kk < 4; kk++) {
                #pragma unroll
                for (int j2 = 0; j2 < 4; j2++) {
                    unsigned r0, r1, r2, r3;
                    ldsm4(r0, r1, r2, r3, Kh + (j2*16)*ARS + kk*32 + boffK);
                    unsigned bf0[2] = {r0, r1}, bf1[2] = {r2, r3};
                    #pragma unroll
                    for (int mf = 0; mf < 2; mf++) {
                        mma16(s[mf][2*j2], q[mf][kk], bf0);
                        mma16(s[mf][2*j2+1], q[mf][kk], bf1);
                    }
                }
            }

            // online softmax per m-frag (rows g and g+8 within each frag)
            #pragma unroll
            for (int mf = 0; mf < 2; mf++) {
                float mx0 = -1e30f, mx1 = -1e30f;
                #pragma unroll
                for (int nf = 0; nf < 8; nf++) {
                    #pragma unroll
                    for (int j = 0; j < 4; j++) s[mf][nf][j] *= SC;
                    mx0 = fmaxf(mx0, fmaxf(s[mf][nf][0], s[mf][nf][1]));
                    mx1 = fmaxf(mx1, fmaxf(s[mf][nf][2], s[mf][nf][3]));
                }
                mx0 = fmaxf(mx0, __shfl_xor_sync(0xffffffffu, mx0, 1));
                mx0 = fmaxf(mx0, __shfl_xor_sync(0xffffffffu, mx0, 2));
                mx1 = fmaxf(mx1, __shfl_xor_sync(0xffffffffu, mx1, 1));
                mx1 = fmaxf(mx1, __shfl_xor_sync(0xffffffffu, mx1, 2));
                float M0 = fmaxf(mm[mf][0], mx0), M1 = fmaxf(mm[mf][1], mx1);
                float c0 = ex2f(mm[mf][0] - M0), c1 = ex2f(mm[mf][1] - M1);
                float ls0 = 0.f, ls1 = 0.f;
                #pragma unroll
                for (int nf = 0; nf < 8; nf++) {
                    s[mf][nf][0] = ex2f(s[mf][nf][0] - M0);
                    s[mf][nf][1] = ex2f(s[mf][nf][1] - M0);
                    s[mf][nf][2] = ex2f(s[mf][nf][2] - M1);
                    s[mf][nf][3] = ex2f(s[mf][nf][3] - M1);
                    ls0 += s[mf][nf][0] + s[mf][nf][1];
                    ls1 += s[mf][nf][2] + s[mf][nf][3];
                }
                ls0 += __shfl_xor_sync(0xffffffffu, ls0, 1);
                ls0 += __shfl_xor_sync(0xffffffffu, ls0, 2);
                ls1 += __shfl_xor_sync(0xffffffffu, ls1, 1);
                ls1 += __shfl_xor_sync(0xffffffffu, ls1, 2);
                ll[mf][0] = ll[mf][0]*c0 + ls0;
                ll[mf][1] = ll[mf][1]*c1 + ls1;
                mm[mf][0] = M0; mm[mf][1] = M1;
                #pragma unroll
                for (int nf = 0; nf < 8; nf++) {
                    o[mf][nf][0] *= c0; o[mf][nf][1] *= c0;
                    o[mf][nf][2] *= c1; o[mf][nf][3] *= c1;
                }
            }

            // O += P @ V : V frags shared across m-frags
            #pragma unroll
            for (int kc2 = 0; kc2 < 4; kc2++) {
                unsigned a2[2][4];
                #pragma unroll
                for (int mf = 0; mf < 2; mf++) {
                    a2[mf][0] = pack2(s[mf][2*kc2][0],   s[mf][2*kc2][1]);
                    a2[mf][1] = pack2(s[mf][2*kc2][2],   s[mf][2*kc2][3]);
                    a2[mf][2] = pack2(s[mf][2*kc2+1][0], s[mf][2*kc2+1][1]);
                    a2[mf][3] = pack2(s[mf][2*kc2+1][2], s[mf][2*kc2+1][3]);
                }
                #pragma unroll
                for (int j = 0; j < 4; j++) {
                    unsigned r0, r1, r2, r3;
                    ldsm4t(r0, r1, r2, r3, Vh + (kc2*16)*ARS + j*32 + boffV);
                    unsigned bf0[2] = {r0, r1}, bf1[2] = {r2, r3};
                    #pragma unroll
                    for (int mf = 0; mf < 2; mf++) {
                        mma16(o[mf][2*j], a2[mf], bf0);
                        mma16(o[mf][2*j+1], a2[mf], bf1);
                    }
                }
            }
        }
    }

    const int qrow = qt*128 + w*32;
    #pragma unroll
    for (int mf = 0; mf < 2; mf++) {
        float inv0 = 1.f / ll[mf][0], inv1 = 1.f / ll[mf][1];
        __half* op = g_ctx + (((size_t)(p*BB+b)*HH + h)*NN + qrow + mf*16)*HD;
        #pragma unroll
        for (int nf = 0; nf < 8; nf++) {
            *(__half2*)(op + g*64 + nf*8 + 2*t) =
                __floats2half2_rn(o[mf][nf][0]*inv0, o[mf][nf][1]*inv0);
            *(__half2*)(op + (g+8)*64 + nf*8 + 2*t) =
                __floats2half2_rn(o[mf][nf][2]*inv1, o[mf][nf][3]*inv1);
        }
    }
}

// =====================================================================
// Kernel 3 (r10/r13 winner): projection GEMM, 256 thr = 8 warps (2m x 4n),
// warp tile 64x32, K-step 64 = one head, 3-stage SW128.
// + bias + q-residual -> f32 out.
// =====================================================================
__global__ __launch_bounds__(256, 2) void proj_gemm_mma(
    const float* __restrict__ bias, float* __restrict__ out)
{
    extern __shared__ __align__(16) unsigned char sp[];
    const int tid = threadIdx.x;
    const int warp = tid >> 5, lane = tid & 31;
    const int wm = warp >> 2, wn = warp & 3;
    const int g = lane >> 2, t = lane & 3;
    const int mt = blockIdx.y;
    const int bn = blockIdx.x * 128;
    const unsigned smb = s2u(sp);

    const __half* actx[4]; unsigned ad[4];
    const __half* bsr[4]; unsigned bd[4];
    #pragma unroll
    for (int i = 0; i < 4; i++) {
        int id = tid + i*256, r = id >> 3, ch = id & 7;
        int gm = mt*128 + r;
        int pp = gm >> 12, b2 = (gm >> 10) & 3, n = gm & 1023;
        unsigned sw = SWZ((unsigned)(r*128 + ch*16));
        actx[i] = g_ctx + (size_t)(pp*BB + b2)*PERSB + (size_t)n*HD + ch*8;
        ad[i]   = smb + sw;
        bsr[i]  = g_wp + (size_t)(bn + r)*CC + ch*8;
        bd[i]   = smb + GTILE2 + sw;
    }
    const unsigned aoffl = (lane & 15)*128 + (lane >> 4)*16;
    const unsigned blinl = ((lane & 7) + ((lane >> 4) & 1)*8)*128 + ((lane >> 3) & 1)*16;

    float acc[4][4][4] = {};

    #pragma unroll
    for (int st = 0; st < 2; st++) {
        #pragma unroll
        for (int i = 0; i < 4; i++) {
            cp16(ad[i] + st*GSTG2, actx[i] + (size_t)st*(NN*HD));
            cp16(bd[i] + st*GSTG2, bsr[i] + st*64);
        }
        CPCOMMIT();
    }

    unsigned rdo = 0, wro = 2*GSTG2;
    for (int c = 0; c < 12; c++) {
        if (c < 11) { asm volatile("cp.async.wait_group 1;"); }
        else        { asm volatile("cp.async.wait_group 0;"); }
        __syncthreads();
        if (c < 10) {
            #pragma unroll
            for (int i = 0; i < 4; i++) {
                cp16(ad[i] + wro, actx[i] + (size_t)(c+2)*(NN*HD));
                cp16(bd[i] + wro, bsr[i] + (c+2)*64);
            }
            CPCOMMIT();
            wro += GSTG2; if (wro == 3*GSTG2) wro = 0;
        }
        const unsigned Ab = smb + rdo;
        const unsigned Bb = Ab + GTILE2;
        rdo += GSTG2; if (rdo == 3*GSTG2) rdo = 0;
        #pragma unroll
        for (int kk = 0; kk < 4; kk++) {
            const unsigned sa2 = SWZ(aoffl + kk*32);
            const unsigned sb2 = SWZ(blinl + kk*32);
            unsigned a[4][4], bq[4][2];
            #pragma unroll
            for (int mf = 0; mf < 4; mf++)
                ldsm4(a[mf][0], a[mf][1], a[mf][2], a[mf][3],
                      Ab + sa2 + (wm*64 + mf*16)*128);
            #pragma unroll
            for (int g2 = 0; g2 < 2; g2++) {
                unsigned r0, r1, r2, r3;
                ldsm4(r0, r1, r2, r3, Bb + sb2 + (wn*32 + g2*16)*128);
                bq[2*g2][0] = r0; bq[2*g2][1] = r1;
                bq[2*g2+1][0] = r2; bq[2*g2+1][1] = r3;
            }
            #pragma unroll
            for (int mf = 0; mf < 4; mf++)
                #pragma unroll
                for (int nf = 0; nf < 4; nf++)
                    mma16(acc[mf][nf], a[mf], bq[nf]);
        }
    }

    // epilogue: bias + fp16 flat-q residual -> f32 d_out
    #pragma unroll
    for (int mf = 0; mf < 4; mf++) {
        #pragma unroll
        for (int rr = 0; rr < 2; rr++) {
            int gm = mt*128 + wm*64 + mf*16 + g + rr*8;
            int pp = gm >> 12, b2 = (gm >> 10) & 3, n = gm & 1023;
            const __half* qres = g_q + (size_t)((1-pp)*BB + b2)*PERSB + (size_t)n*CC;
            #pragma unroll
            for (int nf = 0; nf < 4; nf++) {
                int col = bn + wn*32 + nf*8 + 2*t;
                float2 qr = __half22float2(*(const __half2*)(qres + col));
                float2 r;
                r.x = acc[mf][nf][2*rr+0] + __ldg(bias + col)   + qr.x;
                r.y = acc[mf][nf][2*rr+1] + __ldg(bias + col+1) + qr.y;
                *(float2*)(out + (size_t)gm*CC + col) = r;
            }
        }
    }
}

// =====================================================================
extern "C" void kernel_launch(void* const* d_in, const int* in_sizes, int n_in,
                              void* d_out, int out_size) {
    const float* before = (const float*)d_in[0];
    const float* after  = (const float*)d_in[1];
    const float* W_qkv  = (const float*)d_in[2];
    const float* ln_g   = (const float*)d_in[3];
    const float* ln_b   = (const float*)d_in[4];
    const float* W_proj = (const float*)d_in[5];
    const float* b_proj = (const float*)d_in[6];
    float* out = (float*)d_out;

    // 0) convert inputs to fp16
    preround_kernel<<<PR8/256, 256>>>(before, after, W_qkv, W_proj);

    // 1) QKV GEMM + register LN: grid (2304/128, 8192/128), 128 thr
    {
        cudaFuncSetAttribute(qkv_gemm_mma, cudaFuncAttributeMaxDynamicSharedMemorySize, GSMEM2);
        dim3 grid(QKV3/128, MROWS/128);
        qkv_gemm_mma<<<grid, 128, GSMEM2>>>(ln_g, ln_b);
    }
    // 2) Attention: 768 blocks, 128 thr (4 warps, 32 q-rows/warp)
    {
        cudaFuncSetAttribute(attn_mma, cudaFuncAttributeMaxDynamicSharedMemorySize, ATTN_SMEM);
        attn_mma<<<768, 128, ATTN_SMEM>>>();
    }
    // 3) Projection GEMM: grid (768/128, 8192/128), 256 thr
    {
        cudaFuncSetAttribute(proj_gemm_mma, cudaFuncAttributeMaxDynamicSharedMemorySize, GSMEM2);
        dim3 grid(CC/128, MROWS/128);
        proj_gemm_mma<<<grid, 256, GSMEM2>>>(b_proj, out);
    }
}